// round 9
// baseline (speedup 1.0000x reference)
#include <cuda_runtime.h>
#include <math.h>
#include <stdint.h>

#define HSZ 1024
#define NHD 16
#define HDM 64
#define SEQ 2048
#define BSZ 2
#define NROWS (BSZ*SEQ)         /* 4096 */
#define NSTAT (BSZ*NHD*SEQ)     /* 65536 */

// -------- scratch (device globals; no allocations allowed) -----------------
__device__ float g_Q [NROWS*HSZ];
__device__ float g_K [NROWS*HSZ];
__device__ float g_V [NROWS*HSZ];
__device__ float g_GK[NROWS*HSZ];
__device__ float g_GQ[BSZ*HSZ];
__device__ float g_gov[NSTAT];
__device__ float g_ent[NSTAT];
__device__ float g_mxp[NSTAT];

// -------- tf32 helpers ------------------------------------------------------
__device__ __forceinline__ float f2tf(float x){
    uint32_t u; asm("cvt.rna.tf32.f32 %0, %1;" : "=r"(u) : "f"(x));
    return __uint_as_float(u);
}
__device__ __forceinline__ void mma8(float c[4], const uint32_t a[4], const uint32_t b[2]){
    asm volatile("mma.sync.aligned.m16n8k8.row.col.f32.tf32.tf32.f32 "
        "{%0,%1,%2,%3}, {%4,%5,%6,%7}, {%8,%9}, {%0,%1,%2,%3};"
        : "+f"(c[0]), "+f"(c[1]), "+f"(c[2]), "+f"(c[3])
        : "r"(a[0]), "r"(a[1]), "r"(a[2]), "r"(a[3]), "r"(b[0]), "r"(b[1]));
}
// permute k within 8-groups so (k, k+4) are adjacent -> LDS.64 fragment loads
__device__ __forceinline__ int pe(int e){ return ((e&3)<<1) | ((e>>2)&1); }

// ===========================================================================
// Projection GEMM (tf32 tensor cores), register-prefetch double buffered:
// store staged regs -> smem, sync, issue next k-tile's global loads (drain
// under the mma block), mma, sync. Hides L2 latency that dominated before.
// out = X[4096,1024] @ W[1024,1024] + b for Q/K/V/GK (z selects matrix).
// ===========================================================================
#define PLA 40    /* As row stride; 40 mod 32 == 8 -> conflict-free */
#define PLB 136   /* Bs row stride; 136 mod 32 == 8 -> conflict-free */

__global__ __launch_bounds__(256) void proj_kernel(
    const float* __restrict__ X,
    const float* __restrict__ Wq, const float* __restrict__ bq,
    const float* __restrict__ Wk, const float* __restrict__ bk,
    const float* __restrict__ Wv, const float* __restrict__ bv,
    const float* __restrict__ Wg, const float* __restrict__ bg)
{
    __shared__ float As[128*PLA];
    __shared__ float Bs[32*PLB];

    const float* W; const float* bias; float* out;
    switch (blockIdx.z) {
        case 0:  W = Wq; bias = bq; out = g_Q;  break;
        case 1:  W = Wk; bias = bk; out = g_K;  break;
        case 2:  W = Wv; bias = bv; out = g_V;  break;
        default: W = Wg; bias = bg; out = g_GK; break;
    }

    const int t = threadIdx.x;
    const int lane = t & 31, warp = t >> 5;
    const int qr = lane >> 2, qc = lane & 3;
    const int wm = warp >> 1, wn = warp & 1;
    const int r0 = blockIdx.y * 128, c0 = blockIdx.x * 128;

    const int ra_r = t >> 3,  ra_c = (t & 7) << 2;     // A: row, k-col
    const int rb_r = t >> 5,  rb_c = (t & 31) << 2;    // B: k-row, n-col

    float acc[2][8][4];
#pragma unroll
    for (int mt = 0; mt < 2; mt++)
#pragma unroll
        for (int nt = 0; nt < 8; nt++)
#pragma unroll
            for (int k = 0; k < 4; k++) acc[mt][nt][k] = 0.f;

    // prime: first k-tile into registers
    float4 ra[4], rb[4];
#pragma unroll
    for (int i = 0; i < 4; i++) {
        ra[i] = *(const float4*)&X[(size_t)(r0 + ra_r + 32*i)*HSZ + ra_c];
        rb[i] = *(const float4*)&W[(size_t)(rb_r + 8*i)*HSZ + c0 + rb_c];
    }

    for (int k0 = 0; k0 < HSZ; k0 += 32) {
        // store staged tile (cvt fused here, unchanged numerics)
#pragma unroll
        for (int i = 0; i < 4; i++) {
            float* p = &As[(ra_r + 32*i)*PLA + (ra_c & ~7)];
            int e = ra_c & 7;
            p[pe(e+0)] = f2tf(ra[i].x); p[pe(e+1)] = f2tf(ra[i].y);
            p[pe(e+2)] = f2tf(ra[i].z); p[pe(e+3)] = f2tf(ra[i].w);
            float4 o = make_float4(f2tf(rb[i].x), f2tf(rb[i].y),
                                   f2tf(rb[i].z), f2tf(rb[i].w));
            *(float4*)&Bs[(rb_r + 8*i)*PLB + rb_c] = o;
        }
        __syncthreads();

        // prefetch next k-tile; loads drain while mma block runs
        if (k0 + 32 < HSZ) {
#pragma unroll
            for (int i = 0; i < 4; i++) {
                ra[i] = *(const float4*)&X[(size_t)(r0 + ra_r + 32*i)*HSZ + k0+32 + ra_c];
                rb[i] = *(const float4*)&W[(size_t)(k0+32 + rb_r + 8*i)*HSZ + c0 + rb_c];
            }
        }

#pragma unroll
        for (int u = 0; u < 4; u++) {
            uint32_t af[2][4];
#pragma unroll
            for (int mt = 0; mt < 2; mt++) {
                int rm = wm*32 + mt*16;
                float2 lo = *(const float2*)&As[(rm+qr  )*PLA + u*8 + 2*qc];
                float2 hi = *(const float2*)&As[(rm+qr+8)*PLA + u*8 + 2*qc];
                af[mt][0] = __float_as_uint(lo.x); af[mt][1] = __float_as_uint(hi.x);
                af[mt][2] = __float_as_uint(lo.y); af[mt][3] = __float_as_uint(hi.y);
            }
#pragma unroll
            for (int nt = 0; nt < 8; nt++) {
                int col = wn*64 + nt*8 + qr;
                uint32_t bb[2];
                bb[0] = __float_as_uint(Bs[(u*8+qc  )*PLB + col]);
                bb[1] = __float_as_uint(Bs[(u*8+qc+4)*PLB + col]);
                mma8(acc[0][nt], af[0], bb);
                mma8(acc[1][nt], af[1], bb);
            }
        }
        __syncthreads();
    }

#pragma unroll
    for (int mt = 0; mt < 2; mt++) {
        int rm = r0 + wm*32 + mt*16;
#pragma unroll
        for (int nt = 0; nt < 8; nt++) {
            int col = c0 + wn*64 + nt*8 + 2*qc;
            float b0 = bias[col], b1 = bias[col+1];
            float2 o;
            o.x = acc[mt][nt][0] + b0; o.y = acc[mt][nt][1] + b1;
            *(float2*)&out[(size_t)(rm+qr)*HSZ + col] = o;
            o.x = acc[mt][nt][2] + b0; o.y = acc[mt][nt][3] + b1;
            *(float2*)&out[(size_t)(rm+qr+8)*HSZ + col] = o;
        }
    }
}

// ===========================================================================
// gq = governance_embeddings[2,1024] @ Wgq + bgq   (tiny, SIMT, fp32)
// ===========================================================================
__global__ void gq_kernel(const float* __restrict__ ge,
                          const float* __restrict__ W,
                          const float* __restrict__ bias)
{
    int c = blockIdx.x * blockDim.x + threadIdx.x;
    int r = blockIdx.y;
    const float* g = ge + (size_t)r * HSZ;
    float a0 = 0.f, a1 = 0.f, a2 = 0.f, a3 = 0.f;
    for (int k = 0; k < HSZ; k += 4) {
        a0 += g[k+0] * W[(size_t)(k+0)*HSZ + c];
        a1 += g[k+1] * W[(size_t)(k+1)*HSZ + c];
        a2 += g[k+2] * W[(size_t)(k+2)*HSZ + c];
        a3 += g[k+3] * W[(size_t)(k+3)*HSZ + c];
    }
    g_GQ[(size_t)r*HSZ + c] = (a0+a1) + (a2+a3) + bias[c];
}

// ===========================================================================
// gov_scores[b,h,s] = sum_d gq[b,h,d]*gk[b,s,h,d]. One warp per output.
// ===========================================================================
__global__ void gov_kernel()
{
    int gw   = (blockIdx.x * blockDim.x + threadIdx.x) >> 5;
    int lane = threadIdx.x & 31;
    if (gw >= NSTAT) return;
    int s  = gw & (SEQ-1);
    int bh = gw >> 11;
    int b = bh >> 4, h = bh & 15;
    const float* gq = g_GQ + (size_t)b*HSZ + h*HDM;
    const float* gk = g_GK + ((size_t)(b*SEQ + s))*HSZ + h*HDM;
    float acc = gq[lane]*gk[lane] + gq[lane+32]*gk[lane+32];
#pragma unroll
    for (int o = 16; o; o >>= 1)
        acc += __shfl_xor_sync(0xffffffffu, acc, o);
    if (lane == 0) g_gov[gw] = acc;
}

// ===========================================================================
// Flash attention, tf32 tensor cores.
// BM=64: 128 threads / 4 warps x 16 rows -> 54.3KB smem -> 4 CTAs/SM.
// 1/8 score scale folded into Q staging (power of two -> bit-exact).
// No P smem bridge: S C-fragment reused directly as the PV A-fragment.
// ===========================================================================
#define ALD 72   /* qs/ks stride: 72 mod 32 == 8 */
#define VLD 68   /* vs stride: 68 mod 32 == 4 -> conflict-free PV B loads */
#define QS_OFF 0
#define KS_OFF (64*ALD)
#define VS_OFF (KS_OFF + 64*ALD)
#define ATT_SMEM ((VS_OFF + 64*VLD)*4)   /* 54272 bytes */

__global__ __launch_bounds__(128) void attn_kernel(float* __restrict__ ctx)
{
    extern __shared__ float sm[];
    float* qs = sm + QS_OFF;   // 64 x 64, k-permuted, pre-scaled by 1/8
    float* ks = sm + KS_OFF;   // 64 x 64, k-permuted
    float* vs = sm + VS_OFF;   // 64 x 64, natural [j][d]

    const int t = threadIdx.x;
    const int lane = t & 31, warp = t >> 5;
    const int qr = lane >> 2, qc = lane & 3;
    const int bh = blockIdx.y, b = bh >> 4, h = bh & 15;
    const int q0 = blockIdx.x * 64;
    const int wr = warp * 16;          // 4 warps x 16 rows

    const float* Qg = g_Q + ((size_t)(b*SEQ + q0))*HSZ + h*HDM;
    const float* Kg = g_K + ((size_t)(b*SEQ))*HSZ + h*HDM;
    const float* Vg = g_V + ((size_t)(b*SEQ))*HSZ + h*HDM;

    // stage Q (coalesced, tf32, permuted, scaled by 1/8 = exact exp shift)
    for (int idx = t; idx < 1024; idx += 128) {
        int r = idx >> 4, c = (idx & 15) << 2;
        float4 v = *(const float4*)&Qg[(size_t)r*HSZ + c];
        float* p = &qs[r*ALD + (c & ~7)];
        int e = c & 7;
        p[pe(e+0)] = 0.125f*f2tf(v.x); p[pe(e+1)] = 0.125f*f2tf(v.y);
        p[pe(e+2)] = 0.125f*f2tf(v.z); p[pe(e+3)] = 0.125f*f2tf(v.w);
    }

    float O[8][4];
    float m[2], Z[2], T[2], E[2];
#pragma unroll
    for (int hi = 0; hi < 2; hi++) { m[hi] = -1e30f; Z[hi] = 0.f; T[hi] = 0.f; E[hi] = 0.f; }
#pragma unroll
    for (int nt = 0; nt < 8; nt++)
#pragma unroll
        for (int k = 0; k < 4; k++) O[nt][k] = 0.f;

    for (int j0 = 0; j0 < SEQ; j0 += 64) {
        __syncthreads();   // prior tile's reads of ks/vs done (also covers Q stage)
        for (int idx = t; idx < 1024; idx += 128) {
            int r = idx >> 4, c = (idx & 15) << 2;
            float4 kv = *(const float4*)&Kg[(size_t)(j0+r)*HSZ + c];
            float* p = &ks[r*ALD + (c & ~7)];
            int e = c & 7;
            p[pe(e+0)] = f2tf(kv.x); p[pe(e+1)] = f2tf(kv.y);
            p[pe(e+2)] = f2tf(kv.z); p[pe(e+3)] = f2tf(kv.w);
            float4 vv = *(const float4*)&Vg[(size_t)(j0+r)*HSZ + c];
            float4 vo = make_float4(f2tf(vv.x), f2tf(vv.y), f2tf(vv.z), f2tf(vv.w));
            *(float4*)&vs[r*VLD + c] = vo;
        }
        __syncthreads();

        // ---- S = (Q/8) @ K^T  (one 16-row m-tile per warp) ----
        float sc[8][4];
#pragma unroll
        for (int nt = 0; nt < 8; nt++)
#pragma unroll
            for (int k = 0; k < 4; k++) sc[nt][k] = 0.f;

#pragma unroll
        for (int u = 0; u < 8; u++) {
            uint32_t qa[4];
            {
                float2 lo = *(const float2*)&qs[(wr+qr  )*ALD + u*8 + 2*qc];
                float2 hi = *(const float2*)&qs[(wr+qr+8)*ALD + u*8 + 2*qc];
                qa[0] = __float_as_uint(lo.x); qa[1] = __float_as_uint(hi.x);
                qa[2] = __float_as_uint(lo.y); qa[3] = __float_as_uint(hi.y);
            }
#pragma unroll
            for (int nt = 0; nt < 8; nt++) {
                float2 kb = *(const float2*)&ks[(nt*8+qr)*ALD + u*8 + 2*qc];
                uint32_t bb[2] = { __float_as_uint(kb.x), __float_as_uint(kb.y) };
                mma8(sc[nt], qa, bb);
            }
        }

        // ---- online softmax + stats (rows wr+qr, wr+qr+8) ----
#pragma unroll
        for (int hi = 0; hi < 2; hi++) {
            float lm = -1e30f;
#pragma unroll
            for (int nt = 0; nt < 8; nt++)
                lm = fmaxf(lm, fmaxf(sc[nt][2*hi], sc[nt][2*hi+1]));
            lm = fmaxf(lm, __shfl_xor_sync(0xffffffffu, lm, 1));
            lm = fmaxf(lm, __shfl_xor_sync(0xffffffffu, lm, 2));
            float mo = m[hi];
            float mn = fmaxf(mo, lm);
            float al = __expf(mo - mn);
            T[hi] = al * (T[hi] + (mo - mn) * Z[hi]);
            Z[hi] *= al;
            E[hi] *= al;
#pragma unroll
            for (int nt = 0; nt < 8; nt++) {
                O[nt][2*hi  ] *= al;
                O[nt][2*hi+1] *= al;
            }
            m[hi] = mn;
            float sp = 0.f, st = 0.f, pm = 0.f;
#pragma unroll
            for (int nt = 0; nt < 8; nt++) {
#pragma unroll
                for (int k = 0; k < 2; k++) {
                    float d = sc[nt][2*hi+k] - mn;
                    float p = __expf(d);
                    sp += p; st += p*d; pm = fmaxf(pm, p);
                    sc[nt][2*hi+k] = f2tf(p);   // rounded for the PV mma
                }
            }
            sp += __shfl_xor_sync(0xffffffffu, sp, 1);
            sp += __shfl_xor_sync(0xffffffffu, sp, 2);
            st += __shfl_xor_sync(0xffffffffu, st, 1);
            st += __shfl_xor_sync(0xffffffffu, st, 2);
            pm  = fmaxf(pm, __shfl_xor_sync(0xffffffffu, pm, 1));
            pm  = fmaxf(pm, __shfl_xor_sync(0xffffffffu, pm, 2));
            Z[hi] += sp; T[hi] += st; E[hi] = fmaxf(E[hi], pm);
        }

        // ---- O += P @ V : sc fragment reused directly as A-fragment ----
#pragma unroll
        for (int u = 0; u < 8; u++) {
            uint32_t pa[4];
            pa[0] = __float_as_uint(sc[u][0]);
            pa[1] = __float_as_uint(sc[u][2]);
            pa[2] = __float_as_uint(sc[u][1]);
            pa[3] = __float_as_uint(sc[u][3]);
#pragma unroll
            for (int nt = 0; nt < 8; nt++) {
                uint32_t bb[2];
                bb[0] = __float_as_uint(vs[(u*8 + 2*qc    )*VLD + nt*8 + qr]);
                bb[1] = __float_as_uint(vs[(u*8 + 2*qc + 1)*VLD + nt*8 + qr]);
                mma8(O[nt], pa, bb);
            }
        }
    }

    // ---- epilogue: normalize, write context + per-row stats ----
#pragma unroll
    for (int hi = 0; hi < 2; hi++) {
        int row = wr + qr + 8*hi;
        float iz = 1.0f / Z[hi];
#pragma unroll
        for (int nt = 0; nt < 8; nt++) {
            float2 o;
            o.x = O[nt][2*hi  ] * iz;
            o.y = O[nt][2*hi+1] * iz;
            *(float2*)&ctx[((size_t)(b*SEQ + q0 + row))*HSZ + h*HDM + nt*8 + 2*qc] = o;
        }
        if (qc == 0) {
            int idx = bh*SEQ + q0 + row;
            g_ent[idx] = logf(Z[hi]) - T[hi]*iz;
            g_mxp[idx] = E[hi]*iz;
        }
    }
}

// ===========================================================================
// Deterministic final reduction: 3 scalar means (no atomics).
// ===========================================================================
__global__ void reduce_kernel(float* __restrict__ out, int n_ctx)
{
    __shared__ float se[512], si[512], sc[512];
    int t = threadIdx.x;
    float e = 0.f, i = 0.f, c = 0.f;
    for (int l = t; l < NSTAT; l += 512) {
        e += g_ent[l];
        i += fabsf(g_gov[l]);
        c += g_mxp[l];
    }
    se[t] = e; si[t] = i; sc[t] = c;
    __syncthreads();
    for (int s2 = 256; s2 > 0; s2 >>= 1) {
        if (t < s2) { se[t] += se[t+s2]; si[t] += si[t+s2]; sc[t] += sc[t+s2]; }
        __syncthreads();
    }
    if (t == 0) {
        const float inv = 1.0f / (float)NSTAT;
        out[n_ctx + 0] = se[0] * inv;
        out[n_ctx + 1] = si[0] * inv;
        out[n_ctx + 2] = sc[0] * inv;
    }
}

// ===========================================================================
extern "C" void kernel_launch(void* const* d_in, const int* in_sizes, int n_in,
                              void* d_out, int out_size)
{
    const float* X   = (const float*)d_in[0];
    const float* GE  = (const float*)d_in[1];
    const float* Wq  = (const float*)d_in[2];  const float* bq  = (const float*)d_in[3];
    const float* Wk  = (const float*)d_in[4];  const float* bk  = (const float*)d_in[5];
    const float* Wv  = (const float*)d_in[6];  const float* bv  = (const float*)d_in[7];
    const float* Wgq = (const float*)d_in[8];  const float* bgq = (const float*)d_in[9];
    const float* Wgk = (const float*)d_in[10]; const float* bgk = (const float*)d_in[11];
    float* out = (float*)d_out;

    cudaFuncSetAttribute(attn_kernel, cudaFuncAttributeMaxDynamicSharedMemorySize, ATT_SMEM);

    proj_kernel<<<dim3(8, 32, 4), 256>>>(X, Wq, bq, Wk, bk, Wv, bv, Wgk, bgk);
    gq_kernel<<<dim3(4, 2), 256>>>(GE, Wgq, bgq);
    gov_kernel<<<NSTAT*32/256, 256>>>();
    attn_kernel<<<dim3(SEQ/64, BSZ*NHD), 128, ATT_SMEM>>>(out);
    reduce_kernel<<<1, 512>>>(out, out_size - 3);
}

// round 10
// speedup vs baseline: 1.0018x; 1.0018x over previous
#include <cuda_runtime.h>
#include <math.h>
#include <stdint.h>

#define HSZ 1024
#define NHD 16
#define HDM 64
#define SEQ 2048
#define BSZ 2
#define NROWS (BSZ*SEQ)         /* 4096 */
#define NSTAT (BSZ*NHD*SEQ)     /* 65536 */

// -------- scratch (device globals; no allocations allowed) -----------------
__device__ float g_Q [NROWS*HSZ];
__device__ float g_K [NROWS*HSZ];
__device__ float g_V [NROWS*HSZ];
__device__ float g_GK[NROWS*HSZ];
__device__ float g_GQ[BSZ*HSZ];
__device__ float g_gov[NSTAT];
__device__ float g_ent[NSTAT];
__device__ float g_mxp[NSTAT];

// -------- tf32 helpers ------------------------------------------------------
__device__ __forceinline__ float f2tf(float x){
    uint32_t u; asm("cvt.rna.tf32.f32 %0, %1;" : "=r"(u) : "f"(x));
    return __uint_as_float(u);
}
__device__ __forceinline__ void mma8(float c[4], const uint32_t a[4], const uint32_t b[2]){
    asm volatile("mma.sync.aligned.m16n8k8.row.col.f32.tf32.tf32.f32 "
        "{%0,%1,%2,%3}, {%4,%5,%6,%7}, {%8,%9}, {%0,%1,%2,%3};"
        : "+f"(c[0]), "+f"(c[1]), "+f"(c[2]), "+f"(c[3])
        : "r"(a[0]), "r"(a[1]), "r"(a[2]), "r"(a[3]), "r"(b[0]), "r"(b[1]));
}
// permute k within 8-groups so (k, k+4) are adjacent -> LDS.64 fragment loads
__device__ __forceinline__ int pe(int e){ return ((e&3)<<1) | ((e>>2)&1); }

// ===========================================================================
// Projection GEMM (tf32 tensor cores), register-prefetch double buffered:
// store staged regs -> smem, sync, issue next k-tile's global loads (drain
// under the mma block), mma, sync. Hides L2 latency that dominated before.
// out = X[4096,1024] @ W[1024,1024] + b for Q/K/V/GK (z selects matrix).
// ===========================================================================
#define PLA 40    /* As row stride; 40 mod 32 == 8 -> conflict-free */
#define PLB 136   /* Bs row stride; 136 mod 32 == 8 -> conflict-free */

__global__ __launch_bounds__(256) void proj_kernel(
    const float* __restrict__ X,
    const float* __restrict__ Wq, const float* __restrict__ bq,
    const float* __restrict__ Wk, const float* __restrict__ bk,
    const float* __restrict__ Wv, const float* __restrict__ bv,
    const float* __restrict__ Wg, const float* __restrict__ bg)
{
    __shared__ float As[128*PLA];
    __shared__ float Bs[32*PLB];

    const float* W; const float* bias; float* out;
    switch (blockIdx.z) {
        case 0:  W = Wq; bias = bq; out = g_Q;  break;
        case 1:  W = Wk; bias = bk; out = g_K;  break;
        case 2:  W = Wv; bias = bv; out = g_V;  break;
        default: W = Wg; bias = bg; out = g_GK; break;
    }

    const int t = threadIdx.x;
    const int lane = t & 31, warp = t >> 5;
    const int qr = lane >> 2, qc = lane & 3;
    const int wm = warp >> 1, wn = warp & 1;
    const int r0 = blockIdx.y * 128, c0 = blockIdx.x * 128;

    const int ra_r = t >> 3,  ra_c = (t & 7) << 2;     // A: row, k-col
    const int rb_r = t >> 5,  rb_c = (t & 31) << 2;    // B: k-row, n-col

    float acc[2][8][4];
#pragma unroll
    for (int mt = 0; mt < 2; mt++)
#pragma unroll
        for (int nt = 0; nt < 8; nt++)
#pragma unroll
            for (int k = 0; k < 4; k++) acc[mt][nt][k] = 0.f;

    // prime: first k-tile into registers
    float4 ra[4], rb[4];
#pragma unroll
    for (int i = 0; i < 4; i++) {
        ra[i] = *(const float4*)&X[(size_t)(r0 + ra_r + 32*i)*HSZ + ra_c];
        rb[i] = *(const float4*)&W[(size_t)(rb_r + 8*i)*HSZ + c0 + rb_c];
    }

    for (int k0 = 0; k0 < HSZ; k0 += 32) {
        // store staged tile (cvt fused here, unchanged numerics)
#pragma unroll
        for (int i = 0; i < 4; i++) {
            float* p = &As[(ra_r + 32*i)*PLA + (ra_c & ~7)];
            int e = ra_c & 7;
            p[pe(e+0)] = f2tf(ra[i].x); p[pe(e+1)] = f2tf(ra[i].y);
            p[pe(e+2)] = f2tf(ra[i].z); p[pe(e+3)] = f2tf(ra[i].w);
            float4 o = make_float4(f2tf(rb[i].x), f2tf(rb[i].y),
                                   f2tf(rb[i].z), f2tf(rb[i].w));
            *(float4*)&Bs[(rb_r + 8*i)*PLB + rb_c] = o;
        }
        __syncthreads();

        // prefetch next k-tile; loads drain while mma block runs
        if (k0 + 32 < HSZ) {
#pragma unroll
            for (int i = 0; i < 4; i++) {
                ra[i] = *(const float4*)&X[(size_t)(r0 + ra_r + 32*i)*HSZ + k0+32 + ra_c];
                rb[i] = *(const float4*)&W[(size_t)(k0+32 + rb_r + 8*i)*HSZ + c0 + rb_c];
            }
        }

#pragma unroll
        for (int u = 0; u < 4; u++) {
            uint32_t af[2][4];
#pragma unroll
            for (int mt = 0; mt < 2; mt++) {
                int rm = wm*32 + mt*16;
                float2 lo = *(const float2*)&As[(rm+qr  )*PLA + u*8 + 2*qc];
                float2 hi = *(const float2*)&As[(rm+qr+8)*PLA + u*8 + 2*qc];
                af[mt][0] = __float_as_uint(lo.x); af[mt][1] = __float_as_uint(hi.x);
                af[mt][2] = __float_as_uint(lo.y); af[mt][3] = __float_as_uint(hi.y);
            }
#pragma unroll
            for (int nt = 0; nt < 8; nt++) {
                int col = wn*64 + nt*8 + qr;
                uint32_t bb[2];
                bb[0] = __float_as_uint(Bs[(u*8+qc  )*PLB + col]);
                bb[1] = __float_as_uint(Bs[(u*8+qc+4)*PLB + col]);
                mma8(acc[0][nt], af[0], bb);
                mma8(acc[1][nt], af[1], bb);
            }
        }
        __syncthreads();
    }

#pragma unroll
    for (int mt = 0; mt < 2; mt++) {
        int rm = r0 + wm*32 + mt*16;
#pragma unroll
        for (int nt = 0; nt < 8; nt++) {
            int col = c0 + wn*64 + nt*8 + 2*qc;
            float b0 = bias[col], b1 = bias[col+1];
            float2 o;
            o.x = acc[mt][nt][0] + b0; o.y = acc[mt][nt][1] + b1;
            *(float2*)&out[(size_t)(rm+qr)*HSZ + col] = o;
            o.x = acc[mt][nt][2] + b0; o.y = acc[mt][nt][3] + b1;
            *(float2*)&out[(size_t)(rm+qr+8)*HSZ + col] = o;
        }
    }
}

// ===========================================================================
// gq = governance_embeddings[2,1024] @ Wgq + bgq   (tiny, SIMT, fp32)
// ===========================================================================
__global__ void gq_kernel(const float* __restrict__ ge,
                          const float* __restrict__ W,
                          const float* __restrict__ bias)
{
    int c = blockIdx.x * blockDim.x + threadIdx.x;
    int r = blockIdx.y;
    const float* g = ge + (size_t)r * HSZ;
    float a0 = 0.f, a1 = 0.f, a2 = 0.f, a3 = 0.f;
    for (int k = 0; k < HSZ; k += 4) {
        a0 += g[k+0] * W[(size_t)(k+0)*HSZ + c];
        a1 += g[k+1] * W[(size_t)(k+1)*HSZ + c];
        a2 += g[k+2] * W[(size_t)(k+2)*HSZ + c];
        a3 += g[k+3] * W[(size_t)(k+3)*HSZ + c];
    }
    g_GQ[(size_t)r*HSZ + c] = (a0+a1) + (a2+a3) + bias[c];
}

// ===========================================================================
// gov_scores[b,h,s] = sum_d gq[b,h,d]*gk[b,s,h,d]. One warp per output.
// ===========================================================================
__global__ void gov_kernel()
{
    int gw   = (blockIdx.x * blockDim.x + threadIdx.x) >> 5;
    int lane = threadIdx.x & 31;
    if (gw >= NSTAT) return;
    int s  = gw & (SEQ-1);
    int bh = gw >> 11;
    int b = bh >> 4, h = bh & 15;
    const float* gq = g_GQ + (size_t)b*HSZ + h*HDM;
    const float* gk = g_GK + ((size_t)(b*SEQ + s))*HSZ + h*HDM;
    float acc = gq[lane]*gk[lane] + gq[lane+32]*gk[lane+32];
#pragma unroll
    for (int o = 16; o; o >>= 1)
        acc += __shfl_xor_sync(0xffffffffu, acc, o);
    if (lane == 0) g_gov[gw] = acc;
}

// ===========================================================================
// Flash attention, tf32 tensor cores.
// BM=64: 128 threads / 4 warps x 16 rows -> 54.3KB smem -> 4 CTAs/SM.
// 1/8 score scale folded into Q staging (power of two -> bit-exact).
// No P smem bridge: S C-fragment reused directly as the PV A-fragment.
// ===========================================================================
#define ALD 72   /* qs/ks stride: 72 mod 32 == 8 */
#define VLD 68   /* vs stride: 68 mod 32 == 4 -> conflict-free PV B loads */
#define QS_OFF 0
#define KS_OFF (64*ALD)
#define VS_OFF (KS_OFF + 64*ALD)
#define ATT_SMEM ((VS_OFF + 64*VLD)*4)   /* 54272 bytes */

__global__ __launch_bounds__(128) void attn_kernel(float* __restrict__ ctx)
{
    extern __shared__ float sm[];
    float* qs = sm + QS_OFF;   // 64 x 64, k-permuted, pre-scaled by 1/8
    float* ks = sm + KS_OFF;   // 64 x 64, k-permuted
    float* vs = sm + VS_OFF;   // 64 x 64, natural [j][d]

    const int t = threadIdx.x;
    const int lane = t & 31, warp = t >> 5;
    const int qr = lane >> 2, qc = lane & 3;
    const int bh = blockIdx.y, b = bh >> 4, h = bh & 15;
    const int q0 = blockIdx.x * 64;
    const int wr = warp * 16;          // 4 warps x 16 rows

    const float* Qg = g_Q + ((size_t)(b*SEQ + q0))*HSZ + h*HDM;
    const float* Kg = g_K + ((size_t)(b*SEQ))*HSZ + h*HDM;
    const float* Vg = g_V + ((size_t)(b*SEQ))*HSZ + h*HDM;

    // stage Q (coalesced, tf32, permuted, scaled by 1/8 = exact exp shift)
    for (int idx = t; idx < 1024; idx += 128) {
        int r = idx >> 4, c = (idx & 15) << 2;
        float4 v = *(const float4*)&Qg[(size_t)r*HSZ + c];
        float* p = &qs[r*ALD + (c & ~7)];
        int e = c & 7;
        p[pe(e+0)] = 0.125f*f2tf(v.x); p[pe(e+1)] = 0.125f*f2tf(v.y);
        p[pe(e+2)] = 0.125f*f2tf(v.z); p[pe(e+3)] = 0.125f*f2tf(v.w);
    }

    float O[8][4];
    float m[2], Z[2], T[2], E[2];
#pragma unroll
    for (int hi = 0; hi < 2; hi++) { m[hi] = -1e30f; Z[hi] = 0.f; T[hi] = 0.f; E[hi] = 0.f; }
#pragma unroll
    for (int nt = 0; nt < 8; nt++)
#pragma unroll
        for (int k = 0; k < 4; k++) O[nt][k] = 0.f;

    for (int j0 = 0; j0 < SEQ; j0 += 64) {
        __syncthreads();   // prior tile's reads of ks/vs done (also covers Q stage)
        for (int idx = t; idx < 1024; idx += 128) {
            int r = idx >> 4, c = (idx & 15) << 2;
            float4 kv = *(const float4*)&Kg[(size_t)(j0+r)*HSZ + c];
            float* p = &ks[r*ALD + (c & ~7)];
            int e = c & 7;
            p[pe(e+0)] = f2tf(kv.x); p[pe(e+1)] = f2tf(kv.y);
            p[pe(e+2)] = f2tf(kv.z); p[pe(e+3)] = f2tf(kv.w);
            float4 vv = *(const float4*)&Vg[(size_t)(j0+r)*HSZ + c];
            float4 vo = make_float4(f2tf(vv.x), f2tf(vv.y), f2tf(vv.z), f2tf(vv.w));
            *(float4*)&vs[r*VLD + c] = vo;
        }
        __syncthreads();

        // ---- S = (Q/8) @ K^T  (one 16-row m-tile per warp) ----
        float sc[8][4];
#pragma unroll
        for (int nt = 0; nt < 8; nt++)
#pragma unroll
            for (int k = 0; k < 4; k++) sc[nt][k] = 0.f;

#pragma unroll
        for (int u = 0; u < 8; u++) {
            uint32_t qa[4];
            {
                float2 lo = *(const float2*)&qs[(wr+qr  )*ALD + u*8 + 2*qc];
                float2 hi = *(const float2*)&qs[(wr+qr+8)*ALD + u*8 + 2*qc];
                qa[0] = __float_as_uint(lo.x); qa[1] = __float_as_uint(hi.x);
                qa[2] = __float_as_uint(lo.y); qa[3] = __float_as_uint(hi.y);
            }
#pragma unroll
            for (int nt = 0; nt < 8; nt++) {
                float2 kb = *(const float2*)&ks[(nt*8+qr)*ALD + u*8 + 2*qc];
                uint32_t bb[2] = { __float_as_uint(kb.x), __float_as_uint(kb.y) };
                mma8(sc[nt], qa, bb);
            }
        }

        // ---- online softmax + stats (rows wr+qr, wr+qr+8) ----
#pragma unroll
        for (int hi = 0; hi < 2; hi++) {
            float lm = -1e30f;
#pragma unroll
            for (int nt = 0; nt < 8; nt++)
                lm = fmaxf(lm, fmaxf(sc[nt][2*hi], sc[nt][2*hi+1]));
            lm = fmaxf(lm, __shfl_xor_sync(0xffffffffu, lm, 1));
            lm = fmaxf(lm, __shfl_xor_sync(0xffffffffu, lm, 2));
            float mo = m[hi];
            float mn = fmaxf(mo, lm);
            float al = __expf(mo - mn);
            T[hi] = al * (T[hi] + (mo - mn) * Z[hi]);
            Z[hi] *= al;
            E[hi] *= al;
#pragma unroll
            for (int nt = 0; nt < 8; nt++) {
                O[nt][2*hi  ] *= al;
                O[nt][2*hi+1] *= al;
            }
            m[hi] = mn;
            float sp = 0.f, st = 0.f, pm = 0.f;
#pragma unroll
            for (int nt = 0; nt < 8; nt++) {
#pragma unroll
                for (int k = 0; k < 2; k++) {
                    float d = sc[nt][2*hi+k] - mn;
                    float p = __expf(d);
                    sp += p; st += p*d; pm = fmaxf(pm, p);
                    sc[nt][2*hi+k] = f2tf(p);   // rounded for the PV mma
                }
            }
            sp += __shfl_xor_sync(0xffffffffu, sp, 1);
            sp += __shfl_xor_sync(0xffffffffu, sp, 2);
            st += __shfl_xor_sync(0xffffffffu, st, 1);
            st += __shfl_xor_sync(0xffffffffu, st, 2);
            pm  = fmaxf(pm, __shfl_xor_sync(0xffffffffu, pm, 1));
            pm  = fmaxf(pm, __shfl_xor_sync(0xffffffffu, pm, 2));
            Z[hi] += sp; T[hi] += st; E[hi] = fmaxf(E[hi], pm);
        }

        // ---- O += P @ V : sc fragment reused directly as A-fragment ----
#pragma unroll
        for (int u = 0; u < 8; u++) {
            uint32_t pa[4];
            pa[0] = __float_as_uint(sc[u][0]);
            pa[1] = __float_as_uint(sc[u][2]);
            pa[2] = __float_as_uint(sc[u][1]);
            pa[3] = __float_as_uint(sc[u][3]);
#pragma unroll
            for (int nt = 0; nt < 8; nt++) {
                uint32_t bb[2];
                bb[0] = __float_as_uint(vs[(u*8 + 2*qc    )*VLD + nt*8 + qr]);
                bb[1] = __float_as_uint(vs[(u*8 + 2*qc + 1)*VLD + nt*8 + qr]);
                mma8(O[nt], pa, bb);
            }
        }
    }

    // ---- epilogue: normalize, write context + per-row stats ----
#pragma unroll
    for (int hi = 0; hi < 2; hi++) {
        int row = wr + qr + 8*hi;
        float iz = 1.0f / Z[hi];
#pragma unroll
        for (int nt = 0; nt < 8; nt++) {
            float2 o;
            o.x = O[nt][2*hi  ] * iz;
            o.y = O[nt][2*hi+1] * iz;
            *(float2*)&ctx[((size_t)(b*SEQ + q0 + row))*HSZ + h*HDM + nt*8 + 2*qc] = o;
        }
        if (qc == 0) {
            int idx = bh*SEQ + q0 + row;
            g_ent[idx] = logf(Z[hi]) - T[hi]*iz;
            g_mxp[idx] = E[hi]*iz;
        }
    }
}

// ===========================================================================
// Deterministic final reduction: 3 scalar means (no atomics).
// ===========================================================================
__global__ void reduce_kernel(float* __restrict__ out, int n_ctx)
{
    __shared__ float se[512], si[512], sc[512];
    int t = threadIdx.x;
    float e = 0.f, i = 0.f, c = 0.f;
    for (int l = t; l < NSTAT; l += 512) {
        e += g_ent[l];
        i += fabsf(g_gov[l]);
        c += g_mxp[l];
    }
    se[t] = e; si[t] = i; sc[t] = c;
    __syncthreads();
    for (int s2 = 256; s2 > 0; s2 >>= 1) {
        if (t < s2) { se[t] += se[t+s2]; si[t] += si[t+s2]; sc[t] += sc[t+s2]; }
        __syncthreads();
    }
    if (t == 0) {
        const float inv = 1.0f / (float)NSTAT;
        out[n_ctx + 0] = se[0] * inv;
        out[n_ctx + 1] = si[0] * inv;
        out[n_ctx + 2] = sc[0] * inv;
    }
}

// ===========================================================================
extern "C" void kernel_launch(void* const* d_in, const int* in_sizes, int n_in,
                              void* d_out, int out_size)
{
    const float* X   = (const float*)d_in[0];
    const float* GE  = (const float*)d_in[1];
    const float* Wq  = (const float*)d_in[2];  const float* bq  = (const float*)d_in[3];
    const float* Wk  = (const float*)d_in[4];  const float* bk  = (const float*)d_in[5];
    const float* Wv  = (const float*)d_in[6];  const float* bv  = (const float*)d_in[7];
    const float* Wgq = (const float*)d_in[8];  const float* bgq = (const float*)d_in[9];
    const float* Wgk = (const float*)d_in[10]; const float* bgk = (const float*)d_in[11];
    float* out = (float*)d_out;

    cudaFuncSetAttribute(attn_kernel, cudaFuncAttributeMaxDynamicSharedMemorySize, ATT_SMEM);

    proj_kernel<<<dim3(8, 32, 4), 256>>>(X, Wq, bq, Wk, bk, Wv, bv, Wgk, bgk);
    gq_kernel<<<dim3(4, 2), 256>>>(GE, Wgq, bgq);
    gov_kernel<<<NSTAT*32/256, 256>>>();
    attn_kernel<<<dim3(SEQ/64, BSZ*NHD), 128, ATT_SMEM>>>(out);
    reduce_kernel<<<1, 512>>>(out, out_size - 3);
}

// round 11
// speedup vs baseline: 1.3928x; 1.3903x over previous
#include <cuda_runtime.h>
#include <cuda_fp16.h>
#include <math.h>
#include <stdint.h>

#define HSZ 1024
#define NHD 16
#define HDM 64
#define SEQ 2048
#define BSZ 2
#define NROWS (BSZ*SEQ)
#define NSTAT (BSZ*NHD*SEQ)

// -------- scratch ----------------------------------------------------------
__device__ __half g_Qh[NROWS*HSZ];   // pre-scaled by 1/8
__device__ __half g_Kh[NROWS*HSZ];
__device__ __half g_Vh[NROWS*HSZ];
__device__ float  g_GK[NROWS*HSZ];
__device__ float  g_GQ[BSZ*HSZ];
__device__ float  g_gov[NSTAT];
__device__ float  g_ent[NSTAT];
__device__ float  g_mxp[NSTAT];

// -------- helpers ----------------------------------------------------------
__device__ __forceinline__ uint32_t pack_h2(float lo, float hi){
    uint32_t d; asm("cvt.rn.f16x2.f32 %0, %1, %2;" : "=r"(d) : "f"(hi), "f"(lo));
    return d;   // lower half = lo, upper = hi
}
__device__ __forceinline__ void mma16(float c[4], const uint32_t a[4], uint32_t b0, uint32_t b1){
    asm volatile("mma.sync.aligned.m16n8k16.row.col.f32.f16.f16.f32 "
        "{%0,%1,%2,%3}, {%4,%5,%6,%7}, {%8,%9}, {%0,%1,%2,%3};"
        : "+f"(c[0]), "+f"(c[1]), "+f"(c[2]), "+f"(c[3])
        : "r"(a[0]), "r"(a[1]), "r"(a[2]), "r"(a[3]), "r"(b0), "r"(b1));
}
// word position within an 8-word group: pair (w, w+4) lands adjacent
__device__ __forceinline__ int pe2(int e){ return ((e&3)<<1) | ((e>>2)&1); }

// ===========================================================================
// Projection GEMM, fp16 mma m16n8k16. CTA 128x128, BK=32, 8 warps x 32x64.
// As2: half2 words [128][16w permuted], stride 24 (==8 mod 32, conflict-free).
// Bs2: k-pair-packed words [k2=16][n=128], stride 136 (==8 mod 32).
// z: 0=Q(*1/8,fp16) 1=K(fp16) 2=V(fp16) 3=GK(f32).
// ===========================================================================
#define SA 24
#define SB 136

__global__ __launch_bounds__(256) void proj_kernel(
    const float* __restrict__ X,
    const float* __restrict__ Wq, const float* __restrict__ bq,
    const float* __restrict__ Wk, const float* __restrict__ bk,
    const float* __restrict__ Wv, const float* __restrict__ bv,
    const float* __restrict__ Wg, const float* __restrict__ bg)
{
    __shared__ __align__(16) uint32_t As2[128*SA];
    __shared__ __align__(16) uint32_t Bs2[16*SB];

    const float* W; const float* bias;
    switch (blockIdx.z) {
        case 0:  W = Wq; bias = bq; break;
        case 1:  W = Wk; bias = bk; break;
        case 2:  W = Wv; bias = bv; break;
        default: W = Wg; bias = bg; break;
    }

    const int t = threadIdx.x;
    const int lane = t & 31, warp = t >> 5;
    const int qr = lane >> 2, qc = lane & 3;
    const int wm = warp >> 1, wn = warp & 1;
    const int r0 = blockIdx.y * 128, c0 = blockIdx.x * 128;

    float acc[2][8][4];
#pragma unroll
    for (int mt = 0; mt < 2; mt++)
#pragma unroll
        for (int nt = 0; nt < 8; nt++)
#pragma unroll
            for (int k = 0; k < 4; k++) acc[mt][nt][k] = 0.f;

    for (int k0 = 0; k0 < HSZ; k0 += 32) {
        // stage A: X 128x32 f32 -> permuted half2 words
#pragma unroll
        for (int i = 0; i < 4; i++) {
            int idx = t + i*256;
            int row = idx >> 3, fq = idx & 7;            // float4 #fq
            float4 v = *(const float4*)&X[(size_t)(r0+row)*HSZ + k0 + fq*4];
            uint32_t* p = &As2[row*SA + (fq>>2)*8];
            int e = 2*(fq&3);
            p[pe2(e  )] = pack_h2(v.x, v.y);
            p[pe2(e+1)] = pack_h2(v.z, v.w);
        }
        // stage B: W 32x128 f32 -> k-pair-packed words
#pragma unroll
        for (int i = 0; i < 2; i++) {
            int idx = t + i*256;
            int k2 = idx >> 5, n0 = (idx & 31) << 2;
            const float* w0 = &W[(size_t)(k0 + 2*k2)*HSZ + c0 + n0];
            float4 va = *(const float4*)w0;
            float4 vb = *(const float4*)(w0 + HSZ);
            *(uint4*)&Bs2[k2*SB + n0] = make_uint4(
                pack_h2(va.x, vb.x), pack_h2(va.y, vb.y),
                pack_h2(va.z, vb.z), pack_h2(va.w, vb.w));
        }
        __syncthreads();

#pragma unroll
        for (int u = 0; u < 2; u++) {
            uint32_t af[2][4];
#pragma unroll
            for (int mt = 0; mt < 2; mt++) {
                int rm = wm*32 + mt*16;
                uint2 lo = *(const uint2*)&As2[(rm+qr  )*SA + u*8 + 2*qc];
                uint2 hi = *(const uint2*)&As2[(rm+qr+8)*SA + u*8 + 2*qc];
                af[mt][0] = lo.x; af[mt][1] = hi.x; af[mt][2] = lo.y; af[mt][3] = hi.y;
            }
#pragma unroll
            for (int nt = 0; nt < 8; nt++) {
                int col = wn*64 + nt*8 + qr;
                uint32_t b0 = Bs2[(u*8 + qc    )*SB + col];
                uint32_t b1 = Bs2[(u*8 + qc + 4)*SB + col];
                mma16(acc[0][nt], af[0], b0, b1);
                mma16(acc[1][nt], af[1], b0, b1);
            }
        }
        __syncthreads();
    }

    const int z = blockIdx.z;
#pragma unroll
    for (int mt = 0; mt < 2; mt++) {
        int rm = r0 + wm*32 + mt*16;
#pragma unroll
        for (int nt = 0; nt < 8; nt++) {
            int col = c0 + wn*64 + nt*8 + 2*qc;
            float b0 = bias[col], b1 = bias[col+1];
            if (z < 3) {
                __half* oh = (z==0) ? g_Qh : (z==1) ? g_Kh : g_Vh;
                float s = (z==0) ? 0.125f : 1.0f;
                uint32_t* ow = (uint32_t*)oh;
                ow[((size_t)(rm+qr  )*HSZ + col) >> 1] =
                    pack_h2((acc[mt][nt][0]+b0)*s, (acc[mt][nt][1]+b1)*s);
                ow[((size_t)(rm+qr+8)*HSZ + col) >> 1] =
                    pack_h2((acc[mt][nt][2]+b0)*s, (acc[mt][nt][3]+b1)*s);
            } else {
                float2 o;
                o.x = acc[mt][nt][0] + b0; o.y = acc[mt][nt][1] + b1;
                *(float2*)&g_GK[(size_t)(rm+qr)*HSZ + col] = o;
                o.x = acc[mt][nt][2] + b0; o.y = acc[mt][nt][3] + b1;
                *(float2*)&g_GK[(size_t)(rm+qr+8)*HSZ + col] = o;
            }
        }
    }
}

// ===========================================================================
__global__ void gq_kernel(const float* __restrict__ ge,
                          const float* __restrict__ W,
                          const float* __restrict__ bias)
{
    int c = blockIdx.x * blockDim.x + threadIdx.x;
    int r = blockIdx.y;
    const float* g = ge + (size_t)r * HSZ;
    float a0 = 0.f, a1 = 0.f, a2 = 0.f, a3 = 0.f;
    for (int k = 0; k < HSZ; k += 4) {
        a0 += g[k+0] * W[(size_t)(k+0)*HSZ + c];
        a1 += g[k+1] * W[(size_t)(k+1)*HSZ + c];
        a2 += g[k+2] * W[(size_t)(k+2)*HSZ + c];
        a3 += g[k+3] * W[(size_t)(k+3)*HSZ + c];
    }
    g_GQ[(size_t)r*HSZ + c] = (a0+a1) + (a2+a3) + bias[c];
}

__global__ void gov_kernel()
{
    int gw   = (blockIdx.x * blockDim.x + threadIdx.x) >> 5;
    int lane = threadIdx.x & 31;
    if (gw >= NSTAT) return;
    int s  = gw & (SEQ-1);
    int bh = gw >> 11;
    int b = bh >> 4, h = bh & 15;
    const float* gq = g_GQ + (size_t)b*HSZ + h*HDM;
    const float* gk = g_GK + ((size_t)(b*SEQ + s))*HSZ + h*HDM;
    float acc = gq[lane]*gk[lane] + gq[lane+32]*gk[lane+32];
#pragma unroll
    for (int o = 16; o; o >>= 1)
        acc += __shfl_xor_sync(0xffffffffu, acc, o);
    if (lane == 0) g_gov[gw] = acc;
}

// ===========================================================================
// Flash attention, fp16 mma m16n8k16, fp32 accum. BM=64, 128 thr / 4 warps.
// qsw/ksw: half2 words [row][32w permuted], stride 40 (==8 mod 32).
// vtw: transposed j-pair-packed words [d][j2 permuted], stride 40.
// S C-frag -> PV A-frag via 4 f16x2 packs per k-step. 30KB static smem.
// ===========================================================================
#define SW 40

__global__ __launch_bounds__(128) void attn_kernel(float* __restrict__ ctx)
{
    __shared__ __align__(16) uint32_t qsw[64*SW];
    __shared__ __align__(16) uint32_t ksw[64*SW];
    __shared__ __align__(16) uint32_t vtw[64*SW];

    const int t = threadIdx.x;
    const int lane = t & 31, warp = t >> 5;
    const int qr = lane >> 2, qc = lane & 3;
    const int bh = blockIdx.y, b = bh >> 4, h = bh & 15;
    const int q0 = blockIdx.x * 64;
    const int wr = warp * 16;

    const __half* Qh = g_Qh + ((size_t)(b*SEQ + q0))*HSZ + h*HDM;
    const __half* Kh = g_Kh + ((size_t)(b*SEQ))*HSZ + h*HDM;
    const __half* Vh = g_Vh + ((size_t)(b*SEQ))*HSZ + h*HDM;

    // ---- stage Q once (already fp16, pre-scaled): permuted word copy ----
#pragma unroll
    for (int i = 0; i < 4; i++) {
        int idx = t + i*128;
        int row = idx >> 3, wq = idx & 7;
        uint4 v = *(const uint4*)(Qh + (size_t)row*HSZ + wq*8);
        uint32_t* p = &qsw[row*SW + (wq>>1)*8];
        int e = (wq&1)*4;
        p[pe2(e)] = v.x; p[pe2(e+1)] = v.y; p[pe2(e+2)] = v.z; p[pe2(e+3)] = v.w;
    }

    float O[8][4];
    float m[2], Z[2], T[2], E[2];
#pragma unroll
    for (int hi = 0; hi < 2; hi++) { m[hi] = -1e30f; Z[hi] = 0.f; T[hi] = 0.f; E[hi] = 0.f; }
#pragma unroll
    for (int nt = 0; nt < 8; nt++)
#pragma unroll
        for (int k = 0; k < 4; k++) O[nt][k] = 0.f;

    const int vj2 = t & 31, vd0 = (t >> 5) * 16;
    const int vpos = (vj2 & 24) | pe2(vj2 & 7);

    for (int j0 = 0; j0 < SEQ; j0 += 64) {
        __syncthreads();
        // ---- stage K (permuted word copy) ----
#pragma unroll
        for (int i = 0; i < 4; i++) {
            int idx = t + i*128;
            int row = idx >> 3, wq = idx & 7;
            uint4 v = *(const uint4*)(Kh + (size_t)(j0+row)*HSZ + wq*8);
            uint32_t* p = &ksw[row*SW + (wq>>1)*8];
            int e = (wq&1)*4;
            p[pe2(e)] = v.x; p[pe2(e+1)] = v.y; p[pe2(e+2)] = v.z; p[pe2(e+3)] = v.w;
        }
        // ---- stage V transposed j-pair-packed: vtw[d][j2] ----
        {
            const __half* rp = Vh + (size_t)(j0 + 2*vj2)*HSZ + vd0;
            uint4 a0 = *(const uint4*)(rp);
            uint4 a1 = *(const uint4*)(rp + 8);
            uint4 c0 = *(const uint4*)(rp + HSZ);
            uint4 c1 = *(const uint4*)(rp + HSZ + 8);
            const uint32_t* pa = (const uint32_t*)&a0;
            const uint32_t* pb = (const uint32_t*)&c0;
#pragma unroll
            for (int d = 0; d < 8; d++)
                vtw[(vd0+d)*SW + vpos] =
                    __byte_perm(pa[d>>1], pb[d>>1], (d&1) ? 0x7632 : 0x5410);
            pa = (const uint32_t*)&a1; pb = (const uint32_t*)&c1;
#pragma unroll
            for (int d = 0; d < 8; d++)
                vtw[(vd0+8+d)*SW + vpos] =
                    __byte_perm(pa[d>>1], pb[d>>1], (d&1) ? 0x7632 : 0x5410);
        }
        __syncthreads();

        // ---- S = (Q/8) @ K^T : 4 k16-steps ----
        float sc[8][4];
#pragma unroll
        for (int nt = 0; nt < 8; nt++)
#pragma unroll
            for (int k = 0; k < 4; k++) sc[nt][k] = 0.f;

#pragma unroll
        for (int u = 0; u < 4; u++) {
            uint32_t qa[4];
            uint2 lo = *(const uint2*)&qsw[(wr+qr  )*SW + u*8 + 2*qc];
            uint2 hi = *(const uint2*)&qsw[(wr+qr+8)*SW + u*8 + 2*qc];
            qa[0] = lo.x; qa[1] = hi.x; qa[2] = lo.y; qa[3] = hi.y;
#pragma unroll
            for (int nt = 0; nt < 8; nt++) {
                uint2 kb = *(const uint2*)&ksw[(nt*8+qr)*SW + u*8 + 2*qc];
                mma16(sc[nt], qa, kb.x, kb.y);
            }
        }

        // ---- online softmax + stats ----
#pragma unroll
        for (int hi = 0; hi < 2; hi++) {
            float lm = -1e30f;
#pragma unroll
            for (int nt = 0; nt < 8; nt++)
                lm = fmaxf(lm, fmaxf(sc[nt][2*hi], sc[nt][2*hi+1]));
            lm = fmaxf(lm, __shfl_xor_sync(0xffffffffu, lm, 1));
            lm = fmaxf(lm, __shfl_xor_sync(0xffffffffu, lm, 2));
            float mo = m[hi];
            float mn = fmaxf(mo, lm);
            float al = __expf(mo - mn);
            T[hi] = al * (T[hi] + (mo - mn) * Z[hi]);
            Z[hi] *= al;
            E[hi] *= al;
#pragma unroll
            for (int nt = 0; nt < 8; nt++) {
                O[nt][2*hi  ] *= al;
                O[nt][2*hi+1] *= al;
            }
            m[hi] = mn;
            float sp = 0.f, st = 0.f, pm = 0.f;
#pragma unroll
            for (int nt = 0; nt < 8; nt++) {
#pragma unroll
                for (int k = 0; k < 2; k++) {
                    float d = sc[nt][2*hi+k] - mn;
                    float p = __expf(d);
                    sp += p; st += p*d; pm = fmaxf(pm, p);
                    sc[nt][2*hi+k] = p;
                }
            }
            sp += __shfl_xor_sync(0xffffffffu, sp, 1);
            sp += __shfl_xor_sync(0xffffffffu, sp, 2);
            st += __shfl_xor_sync(0xffffffffu, st, 1);
            st += __shfl_xor_sync(0xffffffffu, st, 2);
            pm  = fmaxf(pm, __shfl_xor_sync(0xffffffffu, pm, 1));
            pm  = fmaxf(pm, __shfl_xor_sync(0xffffffffu, pm, 2));
            Z[hi] += sp; T[hi] += st; E[hi] = fmaxf(E[hi], pm);
        }

        // ---- O += P @ V : pack C-frag pairs as fp16 A-frag ----
#pragma unroll
        for (int u = 0; u < 4; u++) {
            uint32_t pa[4];
            pa[0] = pack_h2(sc[2*u  ][0], sc[2*u  ][1]);
            pa[1] = pack_h2(sc[2*u  ][2], sc[2*u  ][3]);
            pa[2] = pack_h2(sc[2*u+1][0], sc[2*u+1][1]);
            pa[3] = pack_h2(sc[2*u+1][2], sc[2*u+1][3]);
#pragma unroll
            for (int nt = 0; nt < 8; nt++) {
                uint2 vb = *(const uint2*)&vtw[(nt*8+qr)*SW + u*8 + 2*qc];
                mma16(O[nt], pa, vb.x, vb.y);
            }
        }
    }

    // ---- epilogue ----
#pragma unroll
    for (int hi = 0; hi < 2; hi++) {
        int row = wr + qr + 8*hi;
        float iz = 1.0f / Z[hi];
#pragma unroll
        for (int nt = 0; nt < 8; nt++) {
            float2 o;
            o.x = O[nt][2*hi  ] * iz;
            o.y = O[nt][2*hi+1] * iz;
            *(float2*)&ctx[((size_t)(b*SEQ + q0 + row))*HSZ + h*HDM + nt*8 + 2*qc] = o;
        }
        if (qc == 0) {
            int idx = bh*SEQ + q0 + row;
            g_ent[idx] = logf(Z[hi]) - T[hi]*iz;
            g_mxp[idx] = E[hi]*iz;
        }
    }
}

// ===========================================================================
__global__ void reduce_kernel(float* __restrict__ out, int n_ctx)
{
    __shared__ float se[512], si[512], sc2[512];
    int t = threadIdx.x;
    float e = 0.f, i = 0.f, c = 0.f;
    for (int l = t; l < NSTAT; l += 512) {
        e += g_ent[l];
        i += fabsf(g_gov[l]);
        c += g_mxp[l];
    }
    se[t] = e; si[t] = i; sc2[t] = c;
    __syncthreads();
    for (int s2 = 256; s2 > 0; s2 >>= 1) {
        if (t < s2) { se[t] += se[t+s2]; si[t] += si[t+s2]; sc2[t] += sc2[t+s2]; }
        __syncthreads();
    }
    if (t == 0) {
        const float inv = 1.0f / (float)NSTAT;
        out[n_ctx + 0] = se[0] * inv;
        out[n_ctx + 1] = si[0] * inv;
        out[n_ctx + 2] = sc2[0] * inv;
    }
}

// ===========================================================================
extern "C" void kernel_launch(void* const* d_in, const int* in_sizes, int n_in,
                              void* d_out, int out_size)
{
    const float* X   = (const float*)d_in[0];
    const float* GE  = (const float*)d_in[1];
    const float* Wq  = (const float*)d_in[2];  const float* bq  = (const float*)d_in[3];
    const float* Wk  = (const float*)d_in[4];  const float* bk  = (const float*)d_in[5];
    const float* Wv  = (const float*)d_in[6];  const float* bv  = (const float*)d_in[7];
    const float* Wgq = (const float*)d_in[8];  const float* bgq = (const float*)d_in[9];
    const float* Wgk = (const float*)d_in[10]; const float* bgk = (const float*)d_in[11];
    float* out = (float*)d_out;

    proj_kernel<<<dim3(8, 32, 4), 256>>>(X, Wq, bq, Wk, bk, Wv, bv, Wgk, bgk);
    gq_kernel<<<dim3(4, 2), 256>>>(GE, Wgq, bgq);
    gov_kernel<<<NSTAT*32/256, 256>>>();
    attn_kernel<<<dim3(SEQ/64, BSZ*NHD), 128>>>(out);
    reduce_kernel<<<1, 512>>>(out, out_size - 3);
}

// round 14
// speedup vs baseline: 1.4822x; 1.0642x over previous
#include <cuda_runtime.h>
#include <cuda_fp16.h>
#include <math.h>
#include <stdint.h>

#define HSZ 1024
#define NHD 16
#define HDM 64
#define SEQ 2048
#define BSZ 2
#define NROWS (BSZ*SEQ)
#define NSTAT (BSZ*NHD*SEQ)
#define NXW (NROWS*512)            /* X packed words */
#define NWW (512*1024)             /* one W packed words */

// -------- scratch ----------------------------------------------------------
__device__ uint32_t g_Xp[NXW];        // X packed half2, pre-permuted word order
__device__ uint32_t g_Wp[4*NWW];      // W k-pair-packed [k2][n]
__device__ uint32_t g_Qw[NROWS*512];  // Q fp16 (pre-scaled 1/8), permuted words
__device__ uint32_t g_Kw[NROWS*512];  // K fp16, permuted words
__device__ __half   g_Vh[NROWS*HSZ];  // V fp16, natural layout
__device__ float    g_GK[NROWS*HSZ];
__device__ float    g_GQ[BSZ*HSZ];
__device__ float    g_gov[NSTAT];
__device__ float    g_ent[NSTAT];
__device__ float    g_mxp[NSTAT];

// -------- helpers ----------------------------------------------------------
__device__ __forceinline__ uint32_t pack_h2(float lo, float hi){
    uint32_t d; asm("cvt.rn.f16x2.f32 %0, %1, %2;" : "=r"(d) : "f"(hi), "f"(lo));
    return d;
}
__device__ __forceinline__ void mma16(float c[4], const uint32_t a[4], uint32_t b0, uint32_t b1){
    asm volatile("mma.sync.aligned.m16n8k16.row.col.f32.f16.f16.f32 "
        "{%0,%1,%2,%3}, {%4,%5,%6,%7}, {%8,%9}, {%0,%1,%2,%3};"
        : "+f"(c[0]), "+f"(c[1]), "+f"(c[2]), "+f"(c[3])
        : "r"(a[0]), "r"(a[1]), "r"(a[2]), "r"(a[3]), "r"(b0), "r"(b1));
}
__device__ __forceinline__ int pe2(int e){ return ((e&3)<<1) | ((e>>2)&1); }
__device__ __forceinline__ void cp16(void* smem_dst, const void* gmem_src){
    uint32_t s = (uint32_t)__cvta_generic_to_shared(smem_dst);
    asm volatile("cp.async.cg.shared.global [%0], [%1], 16;" :: "r"(s), "l"(gmem_src) : "memory");
}

// ===========================================================================
// One-shot convert/pack: X -> g_Xp (permuted half2 words), W -> g_Wp.
// ===========================================================================
__global__ void cvt_kernel(const float* __restrict__ X,
                           const float* __restrict__ Wq, const float* __restrict__ Wk,
                           const float* __restrict__ Wv, const float* __restrict__ Wg)
{
    const int total = NXW + 4*NWW;
    for (int idx = blockIdx.x*blockDim.x + threadIdx.x; idx < total;
         idx += gridDim.x*blockDim.x) {
        if (idx < NXW) {
            int row = idx >> 9, pos = idx & 511;
            int g = pos >> 3, pp = pos & 7;
            int w = (pp & 1) ? (pp >> 1) + 4 : (pp >> 1);   // inverse pe2
            int k = (g << 4) + 2*w;
            float2 v = *(const float2*)&X[(size_t)row*HSZ + k];
            g_Xp[idx] = pack_h2(v.x, v.y);
        } else {
            int r = idx - NXW;
            int z = r >> 19, rem = r & (NWW-1);
            int k2 = rem >> 10, n = rem & 1023;
            const float* W = (z==0) ? Wq : (z==1) ? Wk : (z==2) ? Wv : Wg;
            g_Wp[r] = pack_h2(W[(size_t)(2*k2)*HSZ + n], W[(size_t)(2*k2+1)*HSZ + n]);
        }
    }
}

// ===========================================================================
// Projection GEMM: fp16 mma m16n8k16, cp.async double-buffered.
// CTA 128x128, BK=32, 8 warps x 32x64. Operands pre-packed in g_Xp/g_Wp.
// As2: [128][24 words] (16 data + 8 pad; 24qr+2qc mod 32 distinct -> cf).
// Bs2: [16][136 words] (==8 mod 32 -> cf).
// z: 0=Q(*1/8, permuted) 1=K(permuted) 2=V(natural) 3=GK(f32).
// ===========================================================================
#define SA 24
#define SB 136

__global__ __launch_bounds__(256) void proj_kernel(
    const float* __restrict__ bq, const float* __restrict__ bk,
    const float* __restrict__ bv, const float* __restrict__ bg)
{
    __shared__ __align__(16) uint32_t As2[2][128*SA];
    __shared__ __align__(16) uint32_t Bs2[2][16*SB];

    const int z = blockIdx.z;
    const float* bias = (z==0) ? bq : (z==1) ? bk : (z==2) ? bv : bg;
    const uint32_t* Wp = g_Wp + (size_t)z*NWW;

    const int t = threadIdx.x;
    const int lane = t & 31, warp = t >> 5;
    const int qr = lane >> 2, qc = lane & 3;
    const int wm = warp >> 1, wn = warp & 1;
    const int r0 = blockIdx.y * 128, c0 = blockIdx.x * 128;

    // per-thread chunk coordinates (2 As chunks + 2 Bs chunks per stage)
    const int a0r = t >> 2,          a0q = (t & 3) << 2;
    const int a1r = (t+256) >> 2,    a1q = a0q;
    const int b0k = t >> 5,          b0q = (t & 31) << 2;
    const int b1k = (t+256) >> 5,    b1q = b0q;

    float acc[2][8][4];
#pragma unroll
    for (int mt = 0; mt < 2; mt++)
#pragma unroll
        for (int nt = 0; nt < 8; nt++)
#pragma unroll
            for (int k = 0; k < 4; k++) acc[mt][nt][k] = 0.f;

#define STAGE(buf, k0) do { \
    cp16(&As2[buf][a0r*SA + a0q], g_Xp + (size_t)(r0+a0r)*512 + ((k0)>>4)*8 + a0q); \
    cp16(&As2[buf][a1r*SA + a1q], g_Xp + (size_t)(r0+a1r)*512 + ((k0)>>4)*8 + a1q); \
    cp16(&Bs2[buf][b0k*SB + b0q], Wp + (size_t)(((k0)>>1)+b0k)*1024 + c0 + b0q); \
    cp16(&Bs2[buf][b1k*SB + b1q], Wp + (size_t)(((k0)>>1)+b1k)*1024 + c0 + b1q); \
    asm volatile("cp.async.commit_group;" ::: "memory"); \
} while(0)

    STAGE(0, 0);
    for (int s = 0; s < 32; s++) {
        const int buf = s & 1;
        if (s < 31) {
            STAGE(buf^1, (s+1)*32);
            asm volatile("cp.async.wait_group 1;" ::: "memory");
        } else {
            asm volatile("cp.async.wait_group 0;" ::: "memory");
        }
        __syncthreads();

#pragma unroll
        for (int u = 0; u < 2; u++) {
            uint32_t af[2][4];
#pragma unroll
            for (int mt = 0; mt < 2; mt++) {
                int rm = wm*32 + mt*16;
                uint2 lo = *(const uint2*)&As2[buf][(rm+qr  )*SA + u*8 + 2*qc];
                uint2 hi = *(const uint2*)&As2[buf][(rm+qr+8)*SA + u*8 + 2*qc];
                af[mt][0] = lo.x; af[mt][1] = hi.x; af[mt][2] = lo.y; af[mt][3] = hi.y;
            }
#pragma unroll
            for (int nt = 0; nt < 8; nt++) {
                int col = wn*64 + nt*8 + qr;
                uint32_t b0 = Bs2[buf][(u*8 + qc    )*SB + col];
                uint32_t b1 = Bs2[buf][(u*8 + qc + 4)*SB + col];
                mma16(acc[0][nt], af[0], b0, b1);
                mma16(acc[1][nt], af[1], b0, b1);
            }
        }
        __syncthreads();
    }
#undef STAGE

    // ---- epilogue ----
#pragma unroll
    for (int mt = 0; mt < 2; mt++) {
        int rm = r0 + wm*32 + mt*16;
#pragma unroll
        for (int nt = 0; nt < 8; nt++) {
            int col = c0 + wn*64 + nt*8 + 2*qc;
            float b0 = bias[col], b1 = bias[col+1];
            if (z < 2) {            // Q or K: permuted fp16 word
                float sc = (z==0) ? 0.125f : 1.0f;
                uint32_t* ow = (z==0) ? g_Qw : g_Kw;
                int pos = ((col >> 4) << 3) | pe2((col & 15) >> 1);
                ow[(size_t)(rm+qr  )*512 + pos] =
                    pack_h2((acc[mt][nt][0]+b0)*sc, (acc[mt][nt][1]+b1)*sc);
                ow[(size_t)(rm+qr+8)*512 + pos] =
                    pack_h2((acc[mt][nt][2]+b0)*sc, (acc[mt][nt][3]+b1)*sc);
            } else if (z == 2) {    // V: natural fp16
                uint32_t* ow = (uint32_t*)g_Vh;
                ow[((size_t)(rm+qr  )*HSZ + col) >> 1] =
                    pack_h2(acc[mt][nt][0]+b0, acc[mt][nt][1]+b1);
                ow[((size_t)(rm+qr+8)*HSZ + col) >> 1] =
                    pack_h2(acc[mt][nt][2]+b0, acc[mt][nt][3]+b1);
            } else {                // GK: f32
                float2 o;
                o.x = acc[mt][nt][0] + b0; o.y = acc[mt][nt][1] + b1;
                *(float2*)&g_GK[(size_t)(rm+qr)*HSZ + col] = o;
                o.x = acc[mt][nt][2] + b0; o.y = acc[mt][nt][3] + b1;
                *(float2*)&g_GK[(size_t)(rm+qr+8)*HSZ + col] = o;
            }
        }
    }
}

// ===========================================================================
__global__ void gq_kernel(const float* __restrict__ ge,
                          const float* __restrict__ W,
                          const float* __restrict__ bias)
{
    int c = blockIdx.x * blockDim.x + threadIdx.x;
    int r = blockIdx.y;
    const float* g = ge + (size_t)r * HSZ;
    float a0 = 0.f, a1 = 0.f, a2 = 0.f, a3 = 0.f;
    for (int k = 0; k < HSZ; k += 4) {
        a0 += g[k+0] * W[(size_t)(k+0)*HSZ + c];
        a1 += g[k+1] * W[(size_t)(k+1)*HSZ + c];
        a2 += g[k+2] * W[(size_t)(k+2)*HSZ + c];
        a3 += g[k+3] * W[(size_t)(k+3)*HSZ + c];
    }
    g_GQ[(size_t)r*HSZ + c] = (a0+a1) + (a2+a3) + bias[c];
}

__global__ void gov_kernel()
{
    int gw   = (blockIdx.x * blockDim.x + threadIdx.x) >> 5;
    int lane = threadIdx.x & 31;
    if (gw >= NSTAT) return;
    int s  = gw & (SEQ-1);
    int bh = gw >> 11;
    int b = bh >> 4, h = bh & 15;
    const float* gq = g_GQ + (size_t)b*HSZ + h*HDM;
    const float* gk = g_GK + ((size_t)(b*SEQ + s))*HSZ + h*HDM;
    float acc = gq[lane]*gk[lane] + gq[lane+32]*gk[lane+32];
#pragma unroll
    for (int o = 16; o; o >>= 1)
        acc += __shfl_xor_sync(0xffffffffu, acc, o);
    if (lane == 0) g_gov[gw] = acc;
}

// ===========================================================================
// Flash attention, fp16 mma m16n8k16, fp32 accum. BM=64, 128 thr / 4 warps.
// Q/K staging is now a straight uint4 copy (producer pre-permuted words).
// ===========================================================================
#define SW 40

__global__ __launch_bounds__(128) void attn_kernel(float* __restrict__ ctx)
{
    __shared__ __align__(16) uint32_t qsw[64*SW];
    __shared__ __align__(16) uint32_t ksw[64*SW];
    __shared__ __align__(16) uint32_t vtw[64*SW];

    const int t = threadIdx.x;
    const int lane = t & 31, warp = t >> 5;
    const int qr = lane >> 2, qc = lane & 3;
    const int bh = blockIdx.y, b = bh >> 4, h = bh & 15;
    const int q0 = blockIdx.x * 64;
    const int wr = warp * 16;

    const uint32_t* Qw = g_Qw + (size_t)(b*SEQ + q0)*512 + h*32;
    const uint32_t* Kw = g_Kw + (size_t)(b*SEQ)*512 + h*32;
    const __half*   Vh = g_Vh + ((size_t)(b*SEQ))*HSZ + h*HDM;

    // ---- stage Q once: straight permuted-word copy ----
#pragma unroll
    for (int i = 0; i < 4; i++) {
        int idx = t + i*128;
        int row = idx >> 3, q = (idx & 7) << 2;
        *(uint4*)&qsw[row*SW + q] = *(const uint4*)(Qw + (size_t)row*512 + q);
    }

    float O[8][4];
    float m[2], Z[2], T[2], E[2];
#pragma unroll
    for (int hi = 0; hi < 2; hi++) { m[hi] = -1e30f; Z[hi] = 0.f; T[hi] = 0.f; E[hi] = 0.f; }
#pragma unroll
    for (int nt = 0; nt < 8; nt++)
#pragma unroll
        for (int k = 0; k < 4; k++) O[nt][k] = 0.f;

    const int vj2 = t & 31, vd0 = (t >> 5) * 16;
    const int vpos = (vj2 & 24) | pe2(vj2 & 7);

    for (int j0 = 0; j0 < SEQ; j0 += 64) {
        __syncthreads();
        // ---- stage K: straight copy ----
#pragma unroll
        for (int i = 0; i < 4; i++) {
            int idx = t + i*128;
            int row = idx >> 3, q = (idx & 7) << 2;
            *(uint4*)&ksw[row*SW + q] = *(const uint4*)(Kw + (size_t)(j0+row)*512 + q);
        }
        // ---- stage V transposed j-pair-packed ----
        {
            const __half* rp = Vh + (size_t)(j0 + 2*vj2)*HSZ + vd0;
            uint4 a0 = *(const uint4*)(rp);
            uint4 a1 = *(const uint4*)(rp + 8);
            uint4 c0v = *(const uint4*)(rp + HSZ);
            uint4 c1v = *(const uint4*)(rp + HSZ + 8);
            const uint32_t* pa = (const uint32_t*)&a0;
            const uint32_t* pb = (const uint32_t*)&c0v;
#pragma unroll
            for (int d = 0; d < 8; d++)
                vtw[(vd0+d)*SW + vpos] =
                    __byte_perm(pa[d>>1], pb[d>>1], (d&1) ? 0x7632 : 0x5410);
            pa = (const uint32_t*)&a1; pb = (const uint32_t*)&c1v;
#pragma unroll
            for (int d = 0; d < 8; d++)
                vtw[(vd0+8+d)*SW + vpos] =
                    __byte_perm(pa[d>>1], pb[d>>1], (d&1) ? 0x7632 : 0x5410);
        }
        __syncthreads();

        // ---- S = (Q/8) @ K^T ----
        float sc[8][4];
#pragma unroll
        for (int nt = 0; nt < 8; nt++)
#pragma unroll
            for (int k = 0; k < 4; k++) sc[nt][k] = 0.f;

#pragma unroll
        for (int u = 0; u < 4; u++) {
            uint32_t qa[4];
            uint2 lo = *(const uint2*)&qsw[(wr+qr  )*SW + u*8 + 2*qc];
            uint2 hi = *(const uint2*)&qsw[(wr+qr+8)*SW + u*8 + 2*qc];
            qa[0] = lo.x; qa[1] = hi.x; qa[2] = lo.y; qa[3] = hi.y;
#pragma unroll
            for (int nt = 0; nt < 8; nt++) {
                uint2 kb = *(const uint2*)&ksw[(nt*8+qr)*SW + u*8 + 2*qc];
                mma16(sc[nt], qa, kb.x, kb.y);
            }
        }

        // ---- online softmax + stats ----
#pragma unroll
        for (int hi = 0; hi < 2; hi++) {
            float lm = -1e30f;
#pragma unroll
            for (int nt = 0; nt < 8; nt++)
                lm = fmaxf(lm, fmaxf(sc[nt][2*hi], sc[nt][2*hi+1]));
            lm = fmaxf(lm, __shfl_xor_sync(0xffffffffu, lm, 1));
            lm = fmaxf(lm, __shfl_xor_sync(0xffffffffu, lm, 2));
            float mo = m[hi];
            float mn = fmaxf(mo, lm);
            float al = __expf(mo - mn);
            T[hi] = al * (T[hi] + (mo - mn) * Z[hi]);
            Z[hi] *= al;
            E[hi] *= al;
#pragma unroll
            for (int nt = 0; nt < 8; nt++) {
                O[nt][2*hi  ] *= al;
                O[nt][2*hi+1] *= al;
            }
            m[hi] = mn;
            float sp = 0.f, st = 0.f, pm = 0.f;
#pragma unroll
            for (int nt = 0; nt < 8; nt++) {
#pragma unroll
                for (int k = 0; k < 2; k++) {
                    float d = sc[nt][2*hi+k] - mn;
                    float p = __expf(d);
                    sp += p; st += p*d; pm = fmaxf(pm, p);
                    sc[nt][2*hi+k] = p;
                }
            }
            sp += __shfl_xor_sync(0xffffffffu, sp, 1);
            sp += __shfl_xor_sync(0xffffffffu, sp, 2);
            st += __shfl_xor_sync(0xffffffffu, st, 1);
            st += __shfl_xor_sync(0xffffffffu, st, 2);
            pm  = fmaxf(pm, __shfl_xor_sync(0xffffffffu, pm, 1));
            pm  = fmaxf(pm, __shfl_xor_sync(0xffffffffu, pm, 2));
            Z[hi] += sp; T[hi] += st; E[hi] = fmaxf(E[hi], pm);
        }

        // ---- O += P @ V ----
#pragma unroll
        for (int u = 0; u < 4; u++) {
            uint32_t pa[4];
            pa[0] = pack_h2(sc[2*u  ][0], sc[2*u  ][1]);
            pa[1] = pack_h2(sc[2*u  ][2], sc[2*u  ][3]);
            pa[2] = pack_h2(sc[2*u+1][0], sc[2*u+1][1]);
            pa[3] = pack_h2(sc[2*u+1][2], sc[2*u+1][3]);
#pragma unroll
            for (int nt = 0; nt < 8; nt++) {
                uint2 vb = *(const uint2*)&vtw[(nt*8+qr)*SW + u*8 + 2*qc];
                mma16(O[nt], pa, vb.x, vb.y);
            }
        }
    }

    // ---- epilogue ----
#pragma unroll
    for (int hi = 0; hi < 2; hi++) {
        int row = wr + qr + 8*hi;
        float iz = 1.0f / Z[hi];
#pragma unroll
        for (int nt = 0; nt < 8; nt++) {
            float2 o;
            o.x = O[nt][2*hi  ] * iz;
            o.y = O[nt][2*hi+1] * iz;
            *(float2*)&ctx[((size_t)(b*SEQ + q0 + row))*HSZ + h*HDM + nt*8 + 2*qc] = o;
        }
        if (qc == 0) {
            int idx = bh*SEQ + q0 + row;
            g_ent[idx] = logf(Z[hi]) - T[hi]*iz;
            g_mxp[idx] = E[hi]*iz;
        }
    }
}

// ===========================================================================
__global__ void reduce_kernel(float* __restrict__ out, int n_ctx)
{
    __shared__ float se[512], si[512], sc2[512];
    int t = threadIdx.x;
    float e = 0.f, i = 0.f, c = 0.f;
    for (int l = t; l < NSTAT; l += 512) {
        e += g_ent[l];
        i += fabsf(g_gov[l]);
        c += g_mxp[l];
    }
    se[t] = e; si[t] = i; sc2[t] = c;
    __syncthreads();
    for (int s2 = 256; s2 > 0; s2 >>= 1) {
        if (t < s2) { se[t] += se[t+s2]; si[t] += si[t+s2]; sc2[t] += sc2[t+s2]; }
        __syncthreads();
    }
    if (t == 0) {
        const float inv = 1.0f / (float)NSTAT;
        out[n_ctx + 0] = se[0] * inv;
        out[n_ctx + 1] = si[0] * inv;
        out[n_ctx + 2] = sc2[0] * inv;
    }
}

// ===========================================================================
extern "C" void kernel_launch(void* const* d_in, const int* in_sizes, int n_in,
                              void* d_out, int out_size)
{
    const float* X   = (const float*)d_in[0];
    const float* GE  = (const float*)d_in[1];
    const float* Wq  = (const float*)d_in[2];  const float* bq  = (const float*)d_in[3];
    const float* Wk  = (const float*)d_in[4];  const float* bk  = (const float*)d_in[5];
    const float* Wv  = (const float*)d_in[6];  const float* bv  = (const float*)d_in[7];
    const float* Wgq = (const float*)d_in[8];  const float* bgq = (const float*)d_in[9];
    const float* Wgk = (const float*)d_in[10]; const float* bgk = (const float*)d_in[11];
    float* out = (float*)d_out;

    cvt_kernel<<<2048, 256>>>(X, Wq, Wk, Wv, Wgk);
    proj_kernel<<<dim3(8, 32, 4), 256>>>(bq, bk, bv, bgk);
    gq_kernel<<<dim3(4, 2), 256>>>(GE, Wgq, bgq);
    gov_kernel<<<NSTAT*32/256, 256>>>();
    attn_kernel<<<dim3(SEQ/64, BSZ*NHD), 128>>>(out);
    reduce_kernel<<<1, 512>>>(out, out_size - 3);
}

// round 16
// speedup vs baseline: 1.7754x; 1.1978x over previous
#include <cuda_runtime.h>
#include <cuda_fp16.h>
#include <math.h>
#include <stdint.h>

#define HSZ 1024
#define NHD 16
#define HDM 64
#define SEQ 2048
#define BSZ 2
#define NROWS (BSZ*SEQ)
#define NSTAT (BSZ*NHD*SEQ)
#define NXW (NROWS*512)            /* X packed words */
#define NWW (512*1024)             /* one W packed words */

// -------- scratch ----------------------------------------------------------
__device__ uint32_t g_Xp[NXW];          // X packed half2, pre-permuted
__device__ uint32_t g_Wp[4*NWW];        // W k-pair-packed [k2][n]
__device__ uint32_t g_Qw[NROWS*512];    // Q fp16 (1/8), permuted words
__device__ uint32_t g_Kw[NROWS*512];    // K fp16, permuted words
__device__ uint32_t g_Vt[BSZ*NHD*64*1024]; // V transposed j-pair-packed per head
__device__ float    g_GK[NROWS*HSZ];
__device__ float    g_GQ[BSZ*HSZ];
__device__ float    g_gov[NSTAT];
__device__ float    g_ent[NSTAT];
__device__ float    g_mxp[NSTAT];

// -------- helpers ----------------------------------------------------------
__device__ __forceinline__ uint32_t pack_h2(float lo, float hi){
    uint32_t d; asm("cvt.rn.f16x2.f32 %0, %1, %2;" : "=r"(d) : "f"(hi), "f"(lo));
    return d;
}
__device__ __forceinline__ void mma16(float c[4], const uint32_t a[4], uint32_t b0, uint32_t b1){
    asm volatile("mma.sync.aligned.m16n8k16.row.col.f32.f16.f16.f32 "
        "{%0,%1,%2,%3}, {%4,%5,%6,%7}, {%8,%9}, {%0,%1,%2,%3};"
        : "+f"(c[0]), "+f"(c[1]), "+f"(c[2]), "+f"(c[3])
        : "r"(a[0]), "r"(a[1]), "r"(a[2]), "r"(a[3]), "r"(b0), "r"(b1));
}
__device__ __forceinline__ int pe2(int e){ return ((e&3)<<1) | ((e>>2)&1); }
__device__ __forceinline__ void cp16(void* smem_dst, const void* gmem_src){
    uint32_t s = (uint32_t)__cvta_generic_to_shared(smem_dst);
    asm volatile("cp.async.cg.shared.global [%0], [%1], 16;" :: "r"(s), "l"(gmem_src) : "memory");
}

// ===========================================================================
// One-shot convert/pack: X -> g_Xp (permuted half2 words), W -> g_Wp.
// ===========================================================================
__global__ void cvt_kernel(const float* __restrict__ X,
                           const float* __restrict__ Wq, const float* __restrict__ Wk,
                           const float* __restrict__ Wv, const float* __restrict__ Wg)
{
    const int total = NXW + 4*NWW;
    for (int idx = blockIdx.x*blockDim.x + threadIdx.x; idx < total;
         idx += gridDim.x*blockDim.x) {
        if (idx < NXW) {
            int row = idx >> 9, pos = idx & 511;
            int g = pos >> 3, pp = pos & 7;
            int w = (pp & 1) ? (pp >> 1) + 4 : (pp >> 1);   // inverse pe2
            int k = (g << 4) + 2*w;
            float2 v = *(const float2*)&X[(size_t)row*HSZ + k];
            g_Xp[idx] = pack_h2(v.x, v.y);
        } else {
            int r = idx - NXW;
            int z = r >> 19, rem = r & (NWW-1);
            int k2 = rem >> 10, n = rem & 1023;
            const float* W = (z==0) ? Wq : (z==1) ? Wk : (z==2) ? Wv : Wg;
            g_Wp[r] = pack_h2(W[(size_t)(2*k2)*HSZ + n], W[(size_t)(2*k2+1)*HSZ + n]);
        }
    }
}

// ===========================================================================
// Projection GEMM: fp16 mma m16n8k16, cp.async double-buffered.
// z: 0=Q(*1/8, permuted) 1=K(permuted) 2=V(transposed j-pair-packed) 3=GK(f32)
// ===========================================================================
#define SA 24
#define SB 136

__global__ __launch_bounds__(256) void proj_kernel(
    const float* __restrict__ bq, const float* __restrict__ bk,
    const float* __restrict__ bv, const float* __restrict__ bg)
{
    __shared__ __align__(16) uint32_t As2[2][128*SA];
    __shared__ __align__(16) uint32_t Bs2[2][16*SB];

    const int z = blockIdx.z;
    const float* bias = (z==0) ? bq : (z==1) ? bk : (z==2) ? bv : bg;
    const uint32_t* Wp = g_Wp + (size_t)z*NWW;

    const int t = threadIdx.x;
    const int lane = t & 31, warp = t >> 5;
    const int qr = lane >> 2, qc = lane & 3;
    const int wm = warp >> 1, wn = warp & 1;
    const int r0 = blockIdx.y * 128, c0 = blockIdx.x * 128;

    const int a0r = t >> 2,          a0q = (t & 3) << 2;
    const int a1r = (t+256) >> 2,    a1q = a0q;
    const int b0k = t >> 5,          b0q = (t & 31) << 2;
    const int b1k = (t+256) >> 5,    b1q = b0q;

    float acc[2][8][4];
#pragma unroll
    for (int mt = 0; mt < 2; mt++)
#pragma unroll
        for (int nt = 0; nt < 8; nt++)
#pragma unroll
            for (int k = 0; k < 4; k++) acc[mt][nt][k] = 0.f;

#define STAGE(buf, k0) do { \
    cp16(&As2[buf][a0r*SA + a0q], g_Xp + (size_t)(r0+a0r)*512 + ((k0)>>4)*8 + a0q); \
    cp16(&As2[buf][a1r*SA + a1q], g_Xp + (size_t)(r0+a1r)*512 + ((k0)>>4)*8 + a1q); \
    cp16(&Bs2[buf][b0k*SB + b0q], Wp + (size_t)(((k0)>>1)+b0k)*1024 + c0 + b0q); \
    cp16(&Bs2[buf][b1k*SB + b1q], Wp + (size_t)(((k0)>>1)+b1k)*1024 + c0 + b1q); \
    asm volatile("cp.async.commit_group;" ::: "memory"); \
} while(0)

    STAGE(0, 0);
    for (int s = 0; s < 32; s++) {
        const int buf = s & 1;
        if (s < 31) {
            STAGE(buf^1, (s+1)*32);
            asm volatile("cp.async.wait_group 1;" ::: "memory");
        } else {
            asm volatile("cp.async.wait_group 0;" ::: "memory");
        }
        __syncthreads();

#pragma unroll
        for (int u = 0; u < 2; u++) {
            uint32_t af[2][4];
#pragma unroll
            for (int mt = 0; mt < 2; mt++) {
                int rm = wm*32 + mt*16;
                uint2 lo = *(const uint2*)&As2[buf][(rm+qr  )*SA + u*8 + 2*qc];
                uint2 hi = *(const uint2*)&As2[buf][(rm+qr+8)*SA + u*8 + 2*qc];
                af[mt][0] = lo.x; af[mt][1] = hi.x; af[mt][2] = lo.y; af[mt][3] = hi.y;
            }
#pragma unroll
            for (int nt = 0; nt < 8; nt++) {
                int col = wn*64 + nt*8 + qr;
                uint32_t b0 = Bs2[buf][(u*8 + qc    )*SB + col];
                uint32_t b1 = Bs2[buf][(u*8 + qc + 4)*SB + col];
                mma16(acc[0][nt], af[0], b0, b1);
                mma16(acc[1][nt], af[1], b0, b1);
            }
        }
        __syncthreads();
    }
#undef STAGE

    // ---- epilogue ----
#pragma unroll
    for (int mt = 0; mt < 2; mt++) {
        int rm = r0 + wm*32 + mt*16;
#pragma unroll
        for (int nt = 0; nt < 8; nt++) {
            int col = c0 + wn*64 + nt*8 + 2*qc;
            float b0 = bias[col], b1 = bias[col+1];
            if (z < 2) {            // Q or K: permuted fp16 word
                float sc = (z==0) ? 0.125f : 1.0f;
                uint32_t* ow = (z==0) ? g_Qw : g_Kw;
                int pos = ((col >> 4) << 3) | pe2((col & 15) >> 1);
                ow[(size_t)(rm+qr  )*512 + pos] =
                    pack_h2((acc[mt][nt][0]+b0)*sc, (acc[mt][nt][1]+b1)*sc);
                ow[(size_t)(rm+qr+8)*512 + pos] =
                    pack_h2((acc[mt][nt][2]+b0)*sc, (acc[mt][nt][3]+b1)*sc);
            } else if (z == 2) {    // V: transposed j-pair-packed per head
                float v0 = acc[mt][nt][0]+b0, v1 = acc[mt][nt][1]+b1;
                float v2 = acc[mt][nt][2]+b0, v3 = acc[mt][nt][3]+b1;
                float p0 = __shfl_xor_sync(0xffffffffu, v0, 4);
                float p1 = __shfl_xor_sync(0xffffffffu, v1, 4);
                float p2 = __shfl_xor_sync(0xffffffffu, v2, 4);
                float p3 = __shfl_xor_sync(0xffffffffu, v3, 4);
                int row_g; uint32_t w0, w1;
                if ((qr & 1) == 0) {    // pair (rm+qr, rm+qr+1)
                    row_g = rm + qr;
                    w0 = pack_h2(v0, p0); w1 = pack_h2(v1, p1);
                } else {                // pair (rm+8+qr-1, rm+8+qr)
                    row_g = rm + 8 + qr - 1;
                    w0 = pack_h2(p2, v2); w1 = pack_h2(p3, v3);
                }
                int bb = row_g >> 11;
                int hh = col >> 6, d = col & 63;
                int j2l = (row_g & 2047) >> 1;
                int pos = (j2l & ~7) | pe2(j2l & 7);
                size_t base = (size_t)(bb*NHD + hh)*64;
                g_Vt[(base + d    )*1024 + pos] = w0;
                g_Vt[(base + d + 1)*1024 + pos] = w1;
            } else {                // GK: f32
                float2 o;
                o.x = acc[mt][nt][0] + b0; o.y = acc[mt][nt][1] + b1;
                *(float2*)&g_GK[(size_t)(rm+qr)*HSZ + col] = o;
                o.x = acc[mt][nt][2] + b0; o.y = acc[mt][nt][3] + b1;
                *(float2*)&g_GK[(size_t)(rm+qr+8)*HSZ + col] = o;
            }
        }
    }
}

// ===========================================================================
__global__ void gq_kernel(const float* __restrict__ ge,
                          const float* __restrict__ W,
                          const float* __restrict__ bias)
{
    int c = blockIdx.x * blockDim.x + threadIdx.x;
    int r = blockIdx.y;
    const float* g = ge + (size_t)r * HSZ;
    float a0 = 0.f, a1 = 0.f, a2 = 0.f, a3 = 0.f;
    for (int k = 0; k < HSZ; k += 4) {
        a0 += g[k+0] * W[(size_t)(k+0)*HSZ + c];
        a1 += g[k+1] * W[(size_t)(k+1)*HSZ + c];
        a2 += g[k+2] * W[(size_t)(k+2)*HSZ + c];
        a3 += g[k+3] * W[(size_t)(k+3)*HSZ + c];
    }
    g_GQ[(size_t)r*HSZ + c] = (a0+a1) + (a2+a3) + bias[c];
}

__global__ void gov_kernel()
{
    int gw   = (blockIdx.x * blockDim.x + threadIdx.x) >> 5;
    int lane = threadIdx.x & 31;
    if (gw >= NSTAT) return;
    int s  = gw & (SEQ-1);
    int bh = gw >> 11;
    int b = bh >> 4, h = bh & 15;
    const float* gq = g_GQ + (size_t)b*HSZ + h*HDM;
    const float* gk = g_GK + ((size_t)(b*SEQ + s))*HSZ + h*HDM;
    float acc = gq[lane]*gk[lane] + gq[lane+32]*gk[lane+32];
#pragma unroll
    for (int o = 16; o; o >>= 1)
        acc += __shfl_xor_sync(0xffffffffu, acc, o);
    if (lane == 0) g_gov[gw] = acc;
}

// ===========================================================================
// Flash attention, fp16 mma m16n8k16. BM=64, 128 thr / 4 warps.
// K/V staged via cp.async double buffer (straight 16B copies, pre-packed
// layouts from proj). 51.2KB dynamic smem -> 4 CTAs/SM.
// ===========================================================================
#define SW 40
#define QS_W 0
#define KS_W(b) (2560 + (b)*2560)
#define VT_W(b) (7680 + (b)*2560)
#define ATT_SMEM (12800*4)

__global__ __launch_bounds__(128) void attn_kernel(float* __restrict__ ctx)
{
    extern __shared__ __align__(16) uint32_t smw[];
    uint32_t* qsw = smw + QS_W;

    const int t = threadIdx.x;
    const int lane = t & 31, warp = t >> 5;
    const int qr = lane >> 2, qc = lane & 3;
    const int bh = blockIdx.y, b = bh >> 4, h = bh & 15;
    const int q0 = blockIdx.x * 64;
    const int wr = warp * 16;

    const uint32_t* Qw = g_Qw + (size_t)(b*SEQ + q0)*512 + h*32;
    const uint32_t* Kw = g_Kw + (size_t)(b*SEQ)*512 + h*32;
    const uint32_t* Vt = g_Vt + (size_t)bh*64*1024;

    // stage Q once (straight permuted-word copy)
#pragma unroll
    for (int i = 0; i < 4; i++) {
        int idx = t + i*128;
        int row = idx >> 3, q = (idx & 7) << 2;
        *(uint4*)&qsw[row*SW + q] = *(const uint4*)(Qw + (size_t)row*512 + q);
    }

    const int sr = t >> 3, sq = (t & 7) << 2;   // staging coords (rows 0..15 +16i)

#define ASTAGE(buf, j0) do { \
    _Pragma("unroll") \
    for (int i = 0; i < 4; i++) { \
        int row = sr + i*16; \
        cp16(&smw[KS_W(buf) + row*SW + sq], Kw + (size_t)((j0)+row)*512 + sq); \
        cp16(&smw[VT_W(buf) + row*SW + sq], Vt + (size_t)row*1024 + ((j0)>>1) + sq); \
    } \
    asm volatile("cp.async.commit_group;" ::: "memory"); \
} while(0)

    float O[8][4];
    float m[2], Z[2], T[2], E[2];
#pragma unroll
    for (int hi = 0; hi < 2; hi++) { m[hi] = -1e30f; Z[hi] = 0.f; T[hi] = 0.f; E[hi] = 0.f; }
#pragma unroll
    for (int nt = 0; nt < 8; nt++)
#pragma unroll
        for (int k = 0; k < 4; k++) O[nt][k] = 0.f;

    ASTAGE(0, 0);

    for (int s = 0; s < SEQ/64; s++) {
        const int buf = s & 1;
        const uint32_t* ksw = smw + KS_W(buf);
        const uint32_t* vtw = smw + VT_W(buf);
        if (s < SEQ/64 - 1) {
            ASTAGE(buf^1, (s+1)*64);
            asm volatile("cp.async.wait_group 1;" ::: "memory");
        } else {
            asm volatile("cp.async.wait_group 0;" ::: "memory");
        }
        __syncthreads();

        // ---- S = (Q/8) @ K^T ----
        float sc[8][4];
#pragma unroll
        for (int nt = 0; nt < 8; nt++)
#pragma unroll
            for (int k = 0; k < 4; k++) sc[nt][k] = 0.f;

#pragma unroll
        for (int u = 0; u < 4; u++) {
            uint32_t qa[4];
            uint2 lo = *(const uint2*)&qsw[(wr+qr  )*SW + u*8 + 2*qc];
            uint2 hi = *(const uint2*)&qsw[(wr+qr+8)*SW + u*8 + 2*qc];
            qa[0] = lo.x; qa[1] = hi.x; qa[2] = lo.y; qa[3] = hi.y;
#pragma unroll
            for (int nt = 0; nt < 8; nt++) {
                uint2 kb = *(const uint2*)&ksw[(nt*8+qr)*SW + u*8 + 2*qc];
                mma16(sc[nt], qa, kb.x, kb.y);
            }
        }

        // ---- online softmax + stats ----
#pragma unroll
        for (int hi = 0; hi < 2; hi++) {
            float lm = -1e30f;
#pragma unroll
            for (int nt = 0; nt < 8; nt++)
                lm = fmaxf(lm, fmaxf(sc[nt][2*hi], sc[nt][2*hi+1]));
            lm = fmaxf(lm, __shfl_xor_sync(0xffffffffu, lm, 1));
            lm = fmaxf(lm, __shfl_xor_sync(0xffffffffu, lm, 2));
            float mo = m[hi];
            float mn = fmaxf(mo, lm);
            float al = __expf(mo - mn);
            T[hi] = al * (T[hi] + (mo - mn) * Z[hi]);
            Z[hi] *= al;
            E[hi] *= al;
#pragma unroll
            for (int nt = 0; nt < 8; nt++) {
                O[nt][2*hi  ] *= al;
                O[nt][2*hi+1] *= al;
            }
            m[hi] = mn;
            float sp = 0.f, st = 0.f, pm = 0.f;
#pragma unroll
            for (int nt = 0; nt < 8; nt++) {
#pragma unroll
                for (int k = 0; k < 2; k++) {
                    float d = sc[nt][2*hi+k] - mn;
                    float p = __expf(d);
                    sp += p; st += p*d; pm = fmaxf(pm, p);
                    sc[nt][2*hi+k] = p;
                }
            }
            sp += __shfl_xor_sync(0xffffffffu, sp, 1);
            sp += __shfl_xor_sync(0xffffffffu, sp, 2);
            st += __shfl_xor_sync(0xffffffffu, st, 1);
            st += __shfl_xor_sync(0xffffffffu, st, 2);
            pm  = fmaxf(pm, __shfl_xor_sync(0xffffffffu, pm, 1));
            pm  = fmaxf(pm, __shfl_xor_sync(0xffffffffu, pm, 2));
            Z[hi] += sp; T[hi] += st; E[hi] = fmaxf(E[hi], pm);
        }

        // ---- O += P @ V ----
#pragma unroll
        for (int u = 0; u < 4; u++) {
            uint32_t pa[4];
            pa[0] = pack_h2(sc[2*u  ][0], sc[2*u  ][1]);
            pa[1] = pack_h2(sc[2*u  ][2], sc[2*u  ][3]);
            pa[2] = pack_h2(sc[2*u+1][0], sc[2*u+1][1]);
            pa[3] = pack_h2(sc[2*u+1][2], sc[2*u+1][3]);
#pragma unroll
            for (int nt = 0; nt < 8; nt++) {
                uint2 vb = *(const uint2*)&vtw[(nt*8+qr)*SW + u*8 + 2*qc];
                mma16(O[nt], pa, vb.x, vb.y);
            }
        }
        __syncthreads();   // all reads of buf done before next ASTAGE overwrites
    }
#undef ASTAGE

    // ---- epilogue ----
#pragma unroll
    for (int hi = 0; hi < 2; hi++) {
        int row = wr + qr + 8*hi;
        float iz = 1.0f / Z[hi];
#pragma unroll
        for (int nt = 0; nt < 8; nt++) {
            float2 o;
            o.x = O[nt][2*hi  ] * iz;
            o.y = O[nt][2*hi+1] * iz;
            *(float2*)&ctx[((size_t)(b*SEQ + q0 + row))*HSZ + h*HDM + nt*8 + 2*qc] = o;
        }
        if (qc == 0) {
            int idx = bh*SEQ + q0 + row;
            g_ent[idx] = logf(Z[hi]) - T[hi]*iz;
            g_mxp[idx] = E[hi]*iz;
        }
    }
}

// ===========================================================================
__global__ void reduce_kernel(float* __restrict__ out, int n_ctx)
{
    __shared__ float se[512], si[512], sc2[512];
    int t = threadIdx.x;
    float e = 0.f, i = 0.f, c = 0.f;
    for (int l = t; l < NSTAT; l += 512) {
        e += g_ent[l];
        i += fabsf(g_gov[l]);
        c += g_mxp[l];
    }
    se[t] = e; si[t] = i; sc2[t] = c;
    __syncthreads();
    for (int s2 = 256; s2 > 0; s2 >>= 1) {
        if (t < s2) { se[t] += se[t+s2]; si[t] += si[t+s2]; sc2[t] += sc2[t+s2]; }
        __syncthreads();
    }
    if (t == 0) {
        const float inv = 1.0f / (float)NSTAT;
        out[n_ctx + 0] = se[0] * inv;
        out[n_ctx + 1] = si[0] * inv;
        out[n_ctx + 2] = sc2[0] * inv;
    }
}

// ===========================================================================
extern "C" void kernel_launch(void* const* d_in, const int* in_sizes, int n_in,
                              void* d_out, int out_size)
{
    const float* X   = (const float*)d_in[0];
    const float* GE  = (const float*)d_in[1];
    const float* Wq  = (const float*)d_in[2];  const float* bq  = (const float*)d_in[3];
    const float* Wk  = (const float*)d_in[4];  const float* bk  = (const float*)d_in[5];
    const float* Wv  = (const float*)d_in[6];  const float* bv  = (const float*)d_in[7];
    const float* Wgq = (const float*)d_in[8];  const float* bgq = (const float*)d_in[9];
    const float* Wgk = (const float*)d_in[10]; const float* bgk = (const float*)d_in[11];
    float* out = (float*)d_out;

    cudaFuncSetAttribute(attn_kernel, cudaFuncAttributeMaxDynamicSharedMemorySize, ATT_SMEM);

    cvt_kernel<<<2048, 256>>>(X, Wq, Wk, Wv, Wgk);
    proj_kernel<<<dim3(8, 32, 4), 256>>>(bq, bk, bv, bgk);
    gq_kernel<<<dim3(4, 2), 256>>>(GE, Wgq, bgq);
    gov_kernel<<<NSTAT*32/256, 256>>>();
    attn_kernel<<<dim3(SEQ/64, BSZ*NHD), 128, ATT_SMEM>>>(out);
    reduce_kernel<<<1, 512>>>(out, out_size - 3);
}